// round 3
// baseline (speedup 1.0000x reference)
#include <cuda_runtime.h>
#include <cuda_bf16.h>

// GraphAttentionLayer:
//   h: (8, 2048, 256) fp32, W: (256, 256) fp32
//   Wh = h @ W  -> viewed as (B=8, T=2048, H=4, D=64), head h = cols [h*64, h*64+64)
//   scores = (Q K^T) / 8, leaky_relu(0.2), softmax over keys, O = P V
//   out: (8, 2048, 256) fp32, head slice written back to contiguous cols.
//
// Scratch: Wh in a __device__ global (64 MB), no allocations.

#define T_LEN   2048
#define B_SZ    8
#define H_CNT   4
#define D_DIM   64
#define IN_DIM  256
#define M_TOT   (B_SZ * T_LEN)        // 16384

__device__ float g_Wh[(size_t)M_TOT * IN_DIM];   // 64 MB scratch

// ---------------------------------------------------------------------------
// GEMM: C[16384,256] = A[16384,256] * B[256,256]
// 64x64 CTA tile, 256 threads, 4x4 microtile, K-tile 16.
// ---------------------------------------------------------------------------
__global__ void __launch_bounds__(256) gat_gemm_kernel(
    const float* __restrict__ A, const float* __restrict__ B)
{
    __shared__ float4 As[16][16];   // As[k][m4]: A rows (transposed in smem)
    __shared__ float4 Bs[16][16];   // Bs[k][n4]

    const int tid = threadIdx.x;
    const int tx = tid & 15;        // 0..15 -> n4
    const int ty = tid >> 4;        // 0..15 -> m4
    const int rowBase = blockIdx.y * 64;
    const int colBase = blockIdx.x * 64;

    float acc[4][4];
#pragma unroll
    for (int i = 0; i < 4; i++)
#pragma unroll
        for (int j = 0; j < 4; j++) acc[i][j] = 0.f;

    for (int k0 = 0; k0 < IN_DIM; k0 += 16) {
        // load A tile: 64 rows x 16 k. thread -> (m = tid>>2, kq = tid&3)
        {
            const int m  = tid >> 2;
            const int kq = tid & 3;
            float4 av = *(const float4*)(A + (size_t)(rowBase + m) * IN_DIM + k0 + kq * 4);
            float* Asf = (float*)As;
            Asf[(kq * 4 + 0) * 64 + m] = av.x;
            Asf[(kq * 4 + 1) * 64 + m] = av.y;
            Asf[(kq * 4 + 2) * 64 + m] = av.z;
            Asf[(kq * 4 + 3) * 64 + m] = av.w;
        }
        // load B tile: 16 k x 64 n
        {
            const int k  = tid >> 4;
            const int n4 = tid & 15;
            Bs[k][n4] = *(const float4*)(B + (size_t)(k0 + k) * IN_DIM + colBase + n4 * 4);
        }
        __syncthreads();

#pragma unroll
        for (int k = 0; k < 16; k++) {
            float4 a = As[k][ty];
            float4 b = Bs[k][tx];
            acc[0][0] += a.x * b.x; acc[0][1] += a.x * b.y; acc[0][2] += a.x * b.z; acc[0][3] += a.x * b.w;
            acc[1][0] += a.y * b.x; acc[1][1] += a.y * b.y; acc[1][2] += a.y * b.z; acc[1][3] += a.y * b.w;
            acc[2][0] += a.z * b.x; acc[2][1] += a.z * b.y; acc[2][2] += a.z * b.z; acc[2][3] += a.z * b.w;
            acc[3][0] += a.w * b.x; acc[3][1] += a.w * b.y; acc[3][2] += a.w * b.z; acc[3][3] += a.w * b.w;
        }
        __syncthreads();
    }

#pragma unroll
    for (int i = 0; i < 4; i++) {
        float4 v = make_float4(acc[i][0], acc[i][1], acc[i][2], acc[i][3]);
        *(float4*)(g_Wh + (size_t)(rowBase + ty * 4 + i) * IN_DIM + colBase + tx * 4) = v;
    }
}

// ---------------------------------------------------------------------------
// Flash-style attention, fp32, no max-subtraction (scores bounded ~15,
// exp fits fp32 easily; softmax ratio identical to reference).
// Grid: (T/128, B*H). 128 threads, thread = one query row.
// ---------------------------------------------------------------------------
__global__ void __launch_bounds__(128) gat_attn_kernel(float* __restrict__ out)
{
    const int bh   = blockIdx.y;
    const int b    = bh >> 2;
    const int head = bh & 3;
    const int q    = blockIdx.x * 128 + threadIdx.x;    // 0..2047

    const float* base = g_Wh + (size_t)b * T_LEN * IN_DIM + head * D_DIM;

    // Q row -> registers (16 float4 = 64 floats)
    float4 q4[16];
    {
        const float4* qr = (const float4*)(base + (size_t)q * IN_DIM);
#pragma unroll
        for (int i = 0; i < 16; i++) q4[i] = qr[i];
    }

    float4 o4[16];
#pragma unroll
    for (int i = 0; i < 16; i++) o4[i] = make_float4(0.f, 0.f, 0.f, 0.f);
    float l = 0.f;

    __shared__ float4 Ks[64 * 16];   // 64 keys x 64 floats = 16 KB

    for (int kt = 0; kt < T_LEN; kt += 64) {
        __syncthreads();
        // cooperative tile load: 1024 float4 / 128 threads = 8 each
#pragma unroll
        for (int i = 0; i < 8; i++) {
            const int idx = threadIdx.x + i * 128;
            const int r = idx >> 4;
            const int c = idx & 15;
            Ks[idx] = *(const float4*)(base + (size_t)(kt + r) * IN_DIM + c * 4);
        }
        __syncthreads();

#pragma unroll 1
        for (int j = 0; j < 64; j++) {
            const float4* kr = &Ks[j * 16];
            float s = 0.f;
#pragma unroll
            for (int i = 0; i < 16; i++) {
                float4 k4 = kr[i];
                s += q4[i].x * k4.x + q4[i].y * k4.y + q4[i].z * k4.z + q4[i].w * k4.w;
            }
            s *= 0.125f;                       // 1/sqrt(64)
            s = (s > 0.f) ? s : 0.2f * s;      // leaky relu
            float p = __expf(s);
            l += p;
#pragma unroll
            for (int i = 0; i < 16; i++) {
                float4 k4 = kr[i];
                o4[i].x += p * k4.x;
                o4[i].y += p * k4.y;
                o4[i].z += p * k4.z;
                o4[i].w += p * k4.w;
            }
        }
    }

    const float inv = 1.0f / l;
    float* orow = out + ((size_t)b * T_LEN + q) * IN_DIM + head * D_DIM;
#pragma unroll
    for (int i = 0; i < 16; i++) {
        float4 v = make_float4(o4[i].x * inv, o4[i].y * inv, o4[i].z * inv, o4[i].w * inv);
        *(float4*)(orow + i * 4) = v;
    }
}

// ---------------------------------------------------------------------------

extern "C" void kernel_launch(void* const* d_in, const int* in_sizes, int n_in,
                              void* d_out, int out_size)
{
    const float* h = (const float*)d_in[0];   // (8, 2048, 256)
    const float* W = (const float*)d_in[1];   // (256, 256)
    float* out = (float*)d_out;               // (8, 2048, 256)

    dim3 g1(IN_DIM / 64, M_TOT / 64);         // (4, 256)
    gat_gemm_kernel<<<g1, 256>>>(h, W);

    dim3 g2(T_LEN / 128, B_SZ * H_CNT);       // (16, 32)
    gat_attn_kernel<<<g2, 128>>>(out);
}

// round 4
// speedup vs baseline: 1.0910x; 1.0910x over previous
#include <cuda_runtime.h>
#include <cuda_bf16.h>

// GraphAttentionLayer:
//   h: (8, 2048, 256) fp32, W: (256, 256) fp32
//   Wh = h @ W  -> viewed as (B=8, T=2048, H=4, D=64)
//   scores = (Q K^T)/8, leaky_relu(0.2), softmax over keys, O = P V
//   out: (8, 2048, 256) fp32.
//
// Attention inner loops use packed fp32x2 FMA (fma.rn.f32x2, sm_100+) to double
// fp32 MAC throughput per fma-pipe slot.

#define T_LEN   2048
#define B_SZ    8
#define H_CNT   4
#define D_DIM   64
#define IN_DIM  256
#define M_TOT   (B_SZ * T_LEN)        // 16384

__device__ float g_Wh[(size_t)M_TOT * IN_DIM];   // 64 MB scratch

typedef unsigned long long u64;

__device__ __forceinline__ u64 ffma2(u64 a, u64 b, u64 c) {
    u64 d;
    asm("fma.rn.f32x2 %0, %1, %2, %3;" : "=l"(d) : "l"(a), "l"(b), "l"(c));
    return d;
}
__device__ __forceinline__ u64 fadd2(u64 a, u64 b) {
    u64 d;
    asm("add.rn.f32x2 %0, %1, %2;" : "=l"(d) : "l"(a), "l"(b));
    return d;
}
__device__ __forceinline__ u64 fmul2(u64 a, u64 b) {
    u64 d;
    asm("mul.rn.f32x2 %0, %1, %2;" : "=l"(d) : "l"(a), "l"(b));
    return d;
}
__device__ __forceinline__ u64 pack2(float lo, float hi) {
    u64 d;
    asm("mov.b64 %0, {%1, %2};" : "=l"(d) : "f"(lo), "f"(hi));
    return d;
}
__device__ __forceinline__ void unpack2(u64 v, float& lo, float& hi) {
    asm("mov.b64 {%0, %1}, %2;" : "=f"(lo), "=f"(hi) : "l"(v));
}

// ---------------------------------------------------------------------------
// GEMM: C[16384,256] = A[16384,256] * B[256,256]
// 64x64 CTA tile, 256 threads, 4x4 microtile, K-tile 16.
// ---------------------------------------------------------------------------
__global__ void __launch_bounds__(256) gat_gemm_kernel(
    const float* __restrict__ A, const float* __restrict__ B)
{
    __shared__ float4 As[16][16];   // As[k][m4]: A rows (transposed in smem)
    __shared__ float4 Bs[16][16];   // Bs[k][n4]

    const int tid = threadIdx.x;
    const int tx = tid & 15;        // 0..15 -> n4
    const int ty = tid >> 4;        // 0..15 -> m4
    const int rowBase = blockIdx.y * 64;
    const int colBase = blockIdx.x * 64;

    float acc[4][4];
#pragma unroll
    for (int i = 0; i < 4; i++)
#pragma unroll
        for (int j = 0; j < 4; j++) acc[i][j] = 0.f;

    for (int k0 = 0; k0 < IN_DIM; k0 += 16) {
        {
            const int m  = tid >> 2;
            const int kq = tid & 3;
            float4 av = *(const float4*)(A + (size_t)(rowBase + m) * IN_DIM + k0 + kq * 4);
            float* Asf = (float*)As;
            Asf[(kq * 4 + 0) * 64 + m] = av.x;
            Asf[(kq * 4 + 1) * 64 + m] = av.y;
            Asf[(kq * 4 + 2) * 64 + m] = av.z;
            Asf[(kq * 4 + 3) * 64 + m] = av.w;
        }
        {
            const int k  = tid >> 4;
            const int n4 = tid & 15;
            Bs[k][n4] = *(const float4*)(B + (size_t)(k0 + k) * IN_DIM + colBase + n4 * 4);
        }
        __syncthreads();

#pragma unroll
        for (int k = 0; k < 16; k++) {
            float4 a = As[k][ty];
            float4 b = Bs[k][tx];
            acc[0][0] += a.x * b.x; acc[0][1] += a.x * b.y; acc[0][2] += a.x * b.z; acc[0][3] += a.x * b.w;
            acc[1][0] += a.y * b.x; acc[1][1] += a.y * b.y; acc[1][2] += a.y * b.z; acc[1][3] += a.y * b.w;
            acc[2][0] += a.z * b.x; acc[2][1] += a.z * b.y; acc[2][2] += a.z * b.z; acc[2][3] += a.z * b.w;
            acc[3][0] += a.w * b.x; acc[3][1] += a.w * b.y; acc[3][2] += a.w * b.z; acc[3][3] += a.w * b.w;
        }
        __syncthreads();
    }

#pragma unroll
    for (int i = 0; i < 4; i++) {
        float4 v = make_float4(acc[i][0], acc[i][1], acc[i][2], acc[i][3]);
        *(float4*)(g_Wh + (size_t)(rowBase + ty * 4 + i) * IN_DIM + colBase + tx * 4) = v;
    }
}

// ---------------------------------------------------------------------------
// Flash-style attention, packed fp32x2 math, no max-subtraction (scores are
// bounded ~15; exp fits fp32 easily; softmax ratio identical to reference).
// Grid: (T/128, B*H). 128 threads, thread = one query row.
// ---------------------------------------------------------------------------
__global__ void __launch_bounds__(128) gat_attn_kernel(float* __restrict__ out)
{
    const int bh   = blockIdx.y;
    const int b    = bh >> 2;
    const int head = bh & 3;
    const int q    = blockIdx.x * 128 + threadIdx.x;    // 0..2047

    const float* base = g_Wh + (size_t)b * T_LEN * IN_DIM + head * D_DIM;

    // Q row -> 32 packed f32x2 registers (64 floats)
    u64 q2[32];
    {
        const ulonglong2* qr = (const ulonglong2*)(base + (size_t)q * IN_DIM);
#pragma unroll
        for (int i = 0; i < 16; i++) {
            ulonglong2 v = qr[i];
            q2[2 * i]     = v.x;
            q2[2 * i + 1] = v.y;
        }
    }

    u64 o2[32];
#pragma unroll
    for (int i = 0; i < 32; i++) o2[i] = 0ull;
    float l = 0.f;

    __shared__ ulonglong2 Ks[64 * 16];   // 64 keys x 64 floats = 16 KB

    for (int kt = 0; kt < T_LEN; kt += 64) {
        __syncthreads();
        // cooperative tile load: 1024 x 16B / 128 threads = 8 each
#pragma unroll
        for (int i = 0; i < 8; i++) {
            const int idx = threadIdx.x + i * 128;
            const int r = idx >> 4;
            const int c = idx & 15;
            Ks[idx] = ((const ulonglong2*)(base + (size_t)(kt + r) * IN_DIM))[c];
        }
        __syncthreads();

#pragma unroll 1
        for (int j = 0; j < 64; j++) {
            const ulonglong2* kr = &Ks[j * 16];

            // score: 32 packed MACs, 4 parallel accumulators
            u64 s0 = 0ull, s1 = 0ull, s2 = 0ull, s3 = 0ull;
#pragma unroll
            for (int i = 0; i < 16; i += 2) {
                ulonglong2 ka = kr[i];
                ulonglong2 kb = kr[i + 1];
                s0 = ffma2(q2[2 * i],     ka.x, s0);
                s1 = ffma2(q2[2 * i + 1], ka.y, s1);
                s2 = ffma2(q2[2 * i + 2], kb.x, s2);
                s3 = ffma2(q2[2 * i + 3], kb.y, s3);
            }
            u64 st = fadd2(fadd2(s0, s2), fadd2(s1, s3));
            float lo, hi;
            unpack2(st, lo, hi);
            float s = (lo + hi) * 0.125f;          // 1/sqrt(64)
            s = (s > 0.f) ? s : 0.2f * s;          // leaky relu
            float p = __expf(s);
            l += p;
            const u64 pb = pack2(p, p);

            // accumulate O: 32 packed MACs, independent chains
#pragma unroll
            for (int i = 0; i < 16; i++) {
                ulonglong2 kk = kr[i];
                o2[2 * i]     = ffma2(pb, kk.x, o2[2 * i]);
                o2[2 * i + 1] = ffma2(pb, kk.y, o2[2 * i + 1]);
            }
        }
    }

    const float inv = 1.0f / l;
    const u64 inv2 = pack2(inv, inv);
    ulonglong2* orow = (ulonglong2*)(out + ((size_t)b * T_LEN + q) * IN_DIM + head * D_DIM);
#pragma unroll
    for (int i = 0; i < 16; i++) {
        ulonglong2 v;
        v.x = fmul2(o2[2 * i],     inv2);
        v.y = fmul2(o2[2 * i + 1], inv2);
        orow[i] = v;
    }
}

// ---------------------------------------------------------------------------

extern "C" void kernel_launch(void* const* d_in, const int* in_sizes, int n_in,
                              void* d_out, int out_size)
{
    const float* h = (const float*)d_in[0];   // (8, 2048, 256)
    const float* W = (const float*)d_in[1];   // (256, 256)
    float* out = (float*)d_out;               // (8, 2048, 256)

    dim3 g1(IN_DIM / 64, M_TOT / 64);         // (4, 256)
    gat_gemm_kernel<<<g1, 256>>>(h, W);

    dim3 g2(T_LEN / 128, B_SZ * H_CNT);       // (16, 32)
    gat_attn_kernel<<<g2, 128>>>(out);
}

// round 6
// speedup vs baseline: 1.1317x; 1.0373x over previous
#include <cuda_runtime.h>
#include <cuda_bf16.h>
#include <cstdint>

// GraphAttentionLayer on GB300 — sm80-style mma.sync tf32 flash attention.
//   h: (8, 2048, 256) fp32, W: (256, 256) fp32
//   Wh = h @ W  -> (B=8, T=2048, H=4, D=64)
//   S = (Q K^T)/8, leaky_relu(0.2), softmax over keys, O = P V
//   out: (8, 2048, 256) fp32

#define T_LEN   2048
#define B_SZ    8
#define H_CNT   4
#define D_DIM   64
#define IN_DIM  256
#define M_TOT   (B_SZ * T_LEN)        // 16384

__device__ float g_Wh[(size_t)M_TOT * IN_DIM];   // 64 MB scratch

// ---------------------------------------------------------------------------
// helpers
// ---------------------------------------------------------------------------
__device__ __forceinline__ uint32_t tf32cvt(float f) {
    uint32_t u;
    asm("cvt.rna.tf32.f32 %0, %1;" : "=r"(u) : "f"(f));
    return u;
}

// D += A * B  (m16n8k8, tf32 in, f32 accum). A row-major, B col-major.
__device__ __forceinline__ void mma8(float* c, const uint32_t* a,
                                     uint32_t b0, uint32_t b1) {
    asm volatile(
        "mma.sync.aligned.m16n8k8.row.col.f32.tf32.tf32.f32 "
        "{%0,%1,%2,%3}, {%4,%5,%6,%7}, {%8,%9}, {%0,%1,%2,%3};"
        : "+f"(c[0]), "+f"(c[1]), "+f"(c[2]), "+f"(c[3])
        : "r"(a[0]), "r"(a[1]), "r"(a[2]), "r"(a[3]), "r"(b0), "r"(b1));
}

__device__ __forceinline__ float leaky_exp(float x) {
    float y = x * 0.125f;                 // 1/sqrt(64)
    y = (y > 0.f) ? y : 0.2f * y;         // leaky relu
    return __expf(y);
}

// ---------------------------------------------------------------------------
// GEMM: Wh = h @ W    (16384x256 * 256x256), fp32 SIMT (small: ~2.1 GFLOP)
// ---------------------------------------------------------------------------
__global__ void __launch_bounds__(256) gat_gemm_kernel(
    const float* __restrict__ A, const float* __restrict__ B)
{
    __shared__ float4 As[16][16];
    __shared__ float4 Bs[16][16];
    const int tid = threadIdx.x;
    const int tx = tid & 15, ty = tid >> 4;
    const int rowBase = blockIdx.y * 64, colBase = blockIdx.x * 64;

    float acc[4][4];
#pragma unroll
    for (int i = 0; i < 4; i++)
#pragma unroll
        for (int j = 0; j < 4; j++) acc[i][j] = 0.f;

    for (int k0 = 0; k0 < IN_DIM; k0 += 16) {
        {
            const int m = tid >> 2, kq = tid & 3;
            float4 av = *(const float4*)(A + (size_t)(rowBase + m) * IN_DIM + k0 + kq * 4);
            float* Asf = (float*)As;
            Asf[(kq * 4 + 0) * 64 + m] = av.x;
            Asf[(kq * 4 + 1) * 64 + m] = av.y;
            Asf[(kq * 4 + 2) * 64 + m] = av.z;
            Asf[(kq * 4 + 3) * 64 + m] = av.w;
        }
        {
            const int k = tid >> 4, n4 = tid & 15;
            Bs[k][n4] = *(const float4*)(B + (size_t)(k0 + k) * IN_DIM + colBase + n4 * 4);
        }
        __syncthreads();
#pragma unroll
        for (int k = 0; k < 16; k++) {
            float4 a = As[k][ty];
            float4 b = Bs[k][tx];
            acc[0][0] += a.x*b.x; acc[0][1] += a.x*b.y; acc[0][2] += a.x*b.z; acc[0][3] += a.x*b.w;
            acc[1][0] += a.y*b.x; acc[1][1] += a.y*b.y; acc[1][2] += a.y*b.z; acc[1][3] += a.y*b.w;
            acc[2][0] += a.z*b.x; acc[2][1] += a.z*b.y; acc[2][2] += a.z*b.z; acc[2][3] += a.z*b.w;
            acc[3][0] += a.w*b.x; acc[3][1] += a.w*b.y; acc[3][2] += a.w*b.z; acc[3][3] += a.w*b.w;
        }
        __syncthreads();
    }
#pragma unroll
    for (int i = 0; i < 4; i++) {
        float4 v = make_float4(acc[i][0], acc[i][1], acc[i][2], acc[i][3]);
        *(float4*)(g_Wh + (size_t)(rowBase + ty * 4 + i) * IN_DIM + colBase + tx * 4) = v;
    }
}

// ---------------------------------------------------------------------------
// Flash attention, mma.sync tf32.
//
// CTA: 256 threads (8 warps), Q-tile = 128 rows (warp w owns rows w*16..+16).
// Key-tile = 64. 32 tiles per CTA. Grid (16, 32 bh).
//
// SMEM (words):
//   Kp @ 0     (4096 w): K[key][d] stored at  d*64 + ((key%8)*8 + key/8) ^ ((d%8)*8)
//              -> B-frags of S-mma load contiguously (LDS.128)
//   Vp @ 4096  (4096 w): V[key][d] stored at  key*64 + ((d%8)*8 + d/8) ^ ((key%8)*8)
//              -> B-frags of PV-mma load contiguously (LDS.128)
//   P  @ 8192  (8 warps x 16 x 65 w): per-warp P buffer (padded rows)
// Total 16512 words = 66048 B -> 2 CTAs/SM.
// ---------------------------------------------------------------------------
#define SK_W  0
#define SV_W  4096
#define SP_W  8192
#define P_STRIDE 65
#define SMEM_WORDS (SP_W + 8 * 16 * P_STRIDE)   // 16512
#define SMEM_BYTES (SMEM_WORDS * 4)             // 66048

__global__ void __launch_bounds__(256, 2) gat_attn_mma(float* __restrict__ out)
{
    extern __shared__ uint32_t smu[];

    const int tid = threadIdx.x;
    const int w   = tid >> 5;
    const int l   = tid & 31;
    const int g   = l >> 2;        // row group 0..7
    const int tig = l & 3;         // thread-in-group

    const int bh = blockIdx.y, b = bh >> 2, head = bh & 3;
    const int qbase = blockIdx.x * 128;

    const float* wh = g_Wh + (size_t)b * T_LEN * IN_DIM + head * D_DIM;

    // ---- Q fragments: 8 k-steps x 4 regs (tf32)
    uint32_t qa[8][4];
    {
        const float* q0 = wh + (size_t)(qbase + w * 16 + g) * IN_DIM;
        const float* q1 = q0 + 8 * IN_DIM;
#pragma unroll
        for (int ks = 0; ks < 8; ks++) {
            const int d = (ks << 3) + tig;
            qa[ks][0] = tf32cvt(q0[d]);
            qa[ks][1] = tf32cvt(q1[d]);
            qa[ks][2] = tf32cvt(q0[d + 4]);
            qa[ks][3] = tf32cvt(q1[d + 4]);
        }
    }

    float o[8][4];
#pragma unroll
    for (int i = 0; i < 8; i++)
#pragma unroll
        for (int j = 0; j < 4; j++) o[i][j] = 0.f;
    float ls0 = 0.f, ls1 = 0.f;

    uint32_t* prow0 = smu + SP_W + w * (16 * P_STRIDE) + g * P_STRIDE;
    uint32_t* prow1 = prow0 + 8 * P_STRIDE;

    const uint32_t gx = (uint32_t)(g ^ tig);   // xor-swizzle block index

    for (int t = 0; t < 32; t++) {
        __syncthreads();    // previous tile fully consumed

        // ---- fill Kp + Vp (same source data, two layouts), tf32-rounded
        {
            const int r  = tid >> 2;            // key row 0..63
            const int dq = (tid & 3) << 4;      // d chunk base
            const float4* src = (const float4*)(wh + (size_t)(t * 64 + r) * IN_DIM + dq);
            const uint32_t rperm = ((r & 7) << 3) | (r >> 3);
            const uint32_t rx8   = (r & 7) << 3;
#pragma unroll
            for (int j = 0; j < 4; j++) {
                float4 v = src[j];
                float vals[4] = {v.x, v.y, v.z, v.w};
#pragma unroll
                for (int m = 0; m < 4; m++) {
                    const int d = dq + j * 4 + m;
                    const uint32_t u = tf32cvt(vals[m]);
                    smu[SK_W + d * 64 + (rperm ^ ((uint32_t)(d & 7) << 3))] = u;
                    smu[SV_W + r * 64 + ((((uint32_t)(d & 7) << 3) | (uint32_t)(d >> 3)) ^ rx8)] = u;
                }
            }
        }
        __syncthreads();

        // ---- S = Q K^T  (m16 x n64 x k64 per warp)
        float s[8][4];
#pragma unroll
        for (int i = 0; i < 8; i++)
#pragma unroll
            for (int j = 0; j < 4; j++) s[i][j] = 0.f;

#pragma unroll
        for (int ks = 0; ks < 8; ks++) {
            const int d0 = (ks << 3) + tig;
            const uint4* kr0 = (const uint4*)(smu + SK_W + d0 * 64 + (gx << 3));
            const uint4* kr1 = (const uint4*)(smu + SK_W + (d0 + 4) * 64 + ((gx ^ 4u) << 3));
            {
                uint4 b0 = kr0[0], b1 = kr1[0];
                mma8(s[0], qa[ks], b0.x, b1.x);
                mma8(s[1], qa[ks], b0.y, b1.y);
                mma8(s[2], qa[ks], b0.z, b1.z);
                mma8(s[3], qa[ks], b0.w, b1.w);
            }
            {
                uint4 b0 = kr0[1], b1 = kr1[1];
                mma8(s[4], qa[ks], b0.x, b1.x);
                mma8(s[5], qa[ks], b0.y, b1.y);
                mma8(s[6], qa[ks], b0.z, b1.z);
                mma8(s[7], qa[ks], b0.w, b1.w);
            }
        }

        // ---- epilogue: scale, leaky, exp, row-sum; P -> SMEM (tf32)
        __syncwarp();       // prior PV loads done before overwriting P
#pragma unroll
        for (int i = 0; i < 8; i++) {
            const int col = (i << 3) + 2 * tig;
            float p0 = leaky_exp(s[i][0]); ls0 += p0; prow0[col]     = tf32cvt(p0);
            float p1 = leaky_exp(s[i][1]); ls0 += p1; prow0[col + 1] = tf32cvt(p1);
            float p2 = leaky_exp(s[i][2]); ls1 += p2; prow1[col]     = tf32cvt(p2);
            float p3 = leaky_exp(s[i][3]); ls1 += p3; prow1[col + 1] = tf32cvt(p3);
        }
        __syncwarp();

        // ---- O += P V  (m16 x n64 x k64 per warp)
#pragma unroll
        for (int ks = 0; ks < 8; ks++) {
            const int k0 = (ks << 3) + tig;
            uint32_t pa[4];
            pa[0] = prow0[k0];
            pa[1] = prow1[k0];
            pa[2] = prow0[k0 + 4];
            pa[3] = prow1[k0 + 4];
            const uint4* vr0 = (const uint4*)(smu + SV_W + k0 * 64 + (gx << 3));
            const uint4* vr1 = (const uint4*)(smu + SV_W + (k0 + 4) * 64 + ((gx ^ 4u) << 3));
            {
                uint4 b0 = vr0[0], b1 = vr1[0];
                mma8(o[0], pa, b0.x, b1.x);
                mma8(o[1], pa, b0.y, b1.y);
                mma8(o[2], pa, b0.z, b1.z);
                mma8(o[3], pa, b0.w, b1.w);
            }
            {
                uint4 b0 = vr0[1], b1 = vr1[1];
                mma8(o[4], pa, b0.x, b1.x);
                mma8(o[5], pa, b0.y, b1.y);
                mma8(o[6], pa, b0.z, b1.z);
                mma8(o[7], pa, b0.w, b1.w);
            }
        }
    }

    // ---- normalize + write out
    ls0 += __shfl_xor_sync(0xffffffffu, ls0, 1);
    ls0 += __shfl_xor_sync(0xffffffffu, ls0, 2);
    ls1 += __shfl_xor_sync(0xffffffffu, ls1, 1);
    ls1 += __shfl_xor_sync(0xffffffffu, ls1, 2);
    const float inv0 = 1.0f / ls0;
    const float inv1 = 1.0f / ls1;

    float* orow0 = out + (size_t)(b * T_LEN + qbase + w * 16 + g) * IN_DIM + head * D_DIM;
    float* orow1 = orow0 + 8 * IN_DIM;
#pragma unroll
    for (int i = 0; i < 8; i++) {
        const int col = (i << 3) + 2 * tig;
        *(float2*)(orow0 + col) = make_float2(o[i][0] * inv0, o[i][1] * inv0);
        *(float2*)(orow1 + col) = make_float2(o[i][2] * inv1, o[i][3] * inv1);
    }
}

// ---------------------------------------------------------------------------

extern "C" void kernel_launch(void* const* d_in, const int* in_sizes, int n_in,
                              void* d_out, int out_size)
{
    const float* h = (const float*)d_in[0];
    const float* W = (const float*)d_in[1];
    float* out = (float*)d_out;

    static bool attr_set = false;
    if (!attr_set) {
        cudaFuncSetAttribute(gat_attn_mma, cudaFuncAttributeMaxDynamicSharedMemorySize, SMEM_BYTES);
        attr_set = true;
    }

    dim3 g1(IN_DIM / 64, M_TOT / 64);          // (4, 256)
    gat_gemm_kernel<<<g1, 256>>>(h, W);

    dim3 g2(T_LEN / 128, B_SZ * H_CNT);        // (16, 32)
    gat_attn_mma<<<g2, 256, SMEM_BYTES>>>(out);
}

// round 7
// speedup vs baseline: 2.6015x; 2.2988x over previous
#include <cuda_runtime.h>
#include <cuda_bf16.h>
#include <cstdint>

// GraphAttentionLayer — mma.sync tf32 flash attention, conflict-free SMEM.
//   h: (8, 2048, 256) fp32, W: (256, 256) fp32
//   Wh = h @ W -> (B=8, T=2048, H=4, D=64)
//   S = (Q K^T)/8, leaky_relu(0.2), softmax over keys, O = P V

#define T_LEN   2048
#define B_SZ    8
#define H_CNT   4
#define D_DIM   64
#define IN_DIM  256
#define M_TOT   (B_SZ * T_LEN)

__device__ float g_Wh[(size_t)M_TOT * IN_DIM];   // 64 MB scratch

// ---------------------------------------------------------------------------
__device__ __forceinline__ uint32_t tf32cvt(float f) {
    uint32_t u;
    asm("cvt.rna.tf32.f32 %0, %1;" : "=r"(u) : "f"(f));
    return u;
}

__device__ __forceinline__ void mma8(float* c, const uint32_t* a,
                                     uint32_t b0, uint32_t b1) {
    asm volatile(
        "mma.sync.aligned.m16n8k8.row.col.f32.tf32.tf32.f32 "
        "{%0,%1,%2,%3}, {%4,%5,%6,%7}, {%8,%9}, {%0,%1,%2,%3};"
        : "+f"(c[0]), "+f"(c[1]), "+f"(c[2]), "+f"(c[3])
        : "r"(a[0]), "r"(a[1]), "r"(a[2]), "r"(a[3]), "r"(b0), "r"(b1));
}

__device__ __forceinline__ float leaky_exp(float x) {
    float y = x * 0.125f;
    y = (y > 0.f) ? y : 0.2f * y;
    return __expf(y);
}

// ---------------------------------------------------------------------------
// GEMM: Wh = h @ W (16384x256 * 256x256)
// ---------------------------------------------------------------------------
__global__ void __launch_bounds__(256) gat_gemm_kernel(
    const float* __restrict__ A, const float* __restrict__ B)
{
    __shared__ float4 As[16][16];
    __shared__ float4 Bs[16][16];
    const int tid = threadIdx.x;
    const int tx = tid & 15, ty = tid >> 4;
    const int rowBase = blockIdx.y * 64, colBase = blockIdx.x * 64;

    float acc[4][4];
#pragma unroll
    for (int i = 0; i < 4; i++)
#pragma unroll
        for (int j = 0; j < 4; j++) acc[i][j] = 0.f;

    for (int k0 = 0; k0 < IN_DIM; k0 += 16) {
        {
            const int m = tid >> 2, kq = tid & 3;
            float4 av = *(const float4*)(A + (size_t)(rowBase + m) * IN_DIM + k0 + kq * 4);
            float* Asf = (float*)As;
            Asf[(kq * 4 + 0) * 64 + m] = av.x;
            Asf[(kq * 4 + 1) * 64 + m] = av.y;
            Asf[(kq * 4 + 2) * 64 + m] = av.z;
            Asf[(kq * 4 + 3) * 64 + m] = av.w;
        }
        {
            const int k = tid >> 4, n4 = tid & 15;
            Bs[k][n4] = *(const float4*)(B + (size_t)(k0 + k) * IN_DIM + colBase + n4 * 4);
        }
        __syncthreads();
#pragma unroll
        for (int k = 0; k < 16; k++) {
            float4 a = As[k][ty];
            float4 b = Bs[k][tx];
            acc[0][0] += a.x*b.x; acc[0][1] += a.x*b.y; acc[0][2] += a.x*b.z; acc[0][3] += a.x*b.w;
            acc[1][0] += a.y*b.x; acc[1][1] += a.y*b.y; acc[1][2] += a.y*b.z; acc[1][3] += a.y*b.w;
            acc[2][0] += a.z*b.x; acc[2][1] += a.z*b.y; acc[2][2] += a.z*b.z; acc[2][3] += a.z*b.w;
            acc[3][0] += a.w*b.x; acc[3][1] += a.w*b.y; acc[3][2] += a.w*b.z; acc[3][3] += a.w*b.w;
        }
        __syncthreads();
    }
#pragma unroll
    for (int i = 0; i < 4; i++) {
        float4 v = make_float4(acc[i][0], acc[i][1], acc[i][2], acc[i][3]);
        *(float4*)(g_Wh + (size_t)(rowBase + ty * 4 + i) * IN_DIM + colBase + tx * 4) = v;
    }
}

// ---------------------------------------------------------------------------
// Flash attention. CTA = 128 threads (4 warps), warp owns 32 queries (2x m16).
// Key-tile 64. 32 tiles. Grid (16, 32).
//
// Layouts (word addresses, P(x) = ((x&7)<<3)|(x>>3), fix(p) = (p&32)>>3):
//   Kp: elem (d,key)  at  d*64  + (P(key) ^ ((d&7)<<3)  ^ fix(P(key)))
//   Vp: elem (key,d)  at  key*64+ (P(d)  ^ ((key&7)<<3) ^ fix(P(d)))
//   Pb (per warp, per m16-half): row*64 + (col ^ ((row&3)<<3) ^ ((row>>2&1)<<2))
// All stores and all fragment loads are bank-conflict-free.
// ---------------------------------------------------------------------------
#define SK_W  0
#define SV_W  4096
#define SP_W  8192
#define SMEM_WORDS 16384
#define SMEM_BYTES (SMEM_WORDS * 4)   // 64 KB

__global__ void __launch_bounds__(128, 2) gat_attn_mma(float* __restrict__ out)
{
    extern __shared__ uint32_t smu[];
    const int tid = threadIdx.x;
    const int w   = tid >> 5;
    const int l   = tid & 31;
    const int g   = l >> 2;
    const int tig = l & 3;

    const int bh = blockIdx.y, b = bh >> 2, head = bh & 3;
    const int qbase = blockIdx.x * 128;
    const float* wh = g_Wh + (size_t)b * T_LEN * IN_DIM + head * D_DIM;

    // ---- Q fragments qa[half][ks][4]
    uint32_t qa[2][8][4];
#pragma unroll
    for (int hh = 0; hh < 2; hh++) {
        const float* q0 = wh + (size_t)(qbase + w * 32 + hh * 16 + g) * IN_DIM;
        const float* q1 = q0 + 8 * IN_DIM;
#pragma unroll
        for (int ks = 0; ks < 8; ks++) {
            const int d = ks * 8 + tig;
            qa[hh][ks][0] = tf32cvt(q0[d]);
            qa[hh][ks][1] = tf32cvt(q1[d]);
            qa[hh][ks][2] = tf32cvt(q0[d + 4]);
            qa[hh][ks][3] = tf32cvt(q1[d + 4]);
        }
    }

    float o[2][8][4];
#pragma unroll
    for (int hh = 0; hh < 2; hh++)
#pragma unroll
        for (int i = 0; i < 8; i++)
#pragma unroll
            for (int j = 0; j < 4; j++) o[hh][i][j] = 0.f;
    float ls[2][2] = {{0.f, 0.f}, {0.f, 0.f}};

    uint32_t* Pw = smu + SP_W + w * 2048;
    const uint32_t swp  = ((uint32_t)(g & 3) << 3) | ((uint32_t)(g >> 2) << 2);
    const uint32_t fixg = (uint32_t)(g & 4);           // = ((8g)&32)>>3

    // fill mappings
    const int fr = tid & 63, fh = tid >> 6;
    const uint32_t posF  = (((uint32_t)fr & 7) << 3) | ((uint32_t)fr >> 3);
    const uint32_t fixF  = (posF & 32) >> 3;

    for (int t = 0; t < 32; t++) {
        __syncthreads();   // previous tile fully consumed

        // ---- pass A: Kp (thread = key fr, d-half fh), conflict-free scalar STS
        {
            const float4* src = (const float4*)(wh + (size_t)(t * 64 + fr) * IN_DIM + fh * 32);
#pragma unroll
            for (int j = 0; j < 8; j++) {
                float4 v = src[j];
                float vals[4] = {v.x, v.y, v.z, v.w};
#pragma unroll
                for (int m = 0; m < 4; m++) {
                    const int d = fh * 32 + j * 4 + m;
                    smu[SK_W + d * 64 + (posF ^ ((uint32_t)(d & 7) << 3) ^ fixF)] = tf32cvt(vals[m]);
                }
            }
        }
        // ---- pass B: Vp (thread = d fr, key-half fh), coalesced LDG + scalar STS
        {
            const float* src = wh + (size_t)(t * 64 + fh * 32) * IN_DIM + fr;
#pragma unroll
            for (int s = 0; s < 32; s++) {
                const int key = fh * 32 + s;
                smu[SV_W + key * 64 + (posF ^ ((uint32_t)(key & 7) << 3) ^ fixF)] =
                    tf32cvt(src[(size_t)s * IN_DIM]);
            }
        }
        __syncthreads();

        // ---- S = Q K^T  (m32 x n64 x k64 per warp)
        float s2[2][8][4];
#pragma unroll
        for (int hh = 0; hh < 2; hh++)
#pragma unroll
            for (int i = 0; i < 8; i++)
#pragma unroll
                for (int j = 0; j < 4; j++) s2[hh][i][j] = 0.f;

#pragma unroll
        for (int ks = 0; ks < 8; ks++) {
            const int d0 = ks * 8 + tig;
            const uint32_t off0 = (8u * g) ^ ((uint32_t)(d0 & 7) << 3) ^ fixg;
            const uint32_t off1 = (8u * g) ^ ((uint32_t)((d0 + 4) & 7) << 3) ^ fixg;
            const uint32_t* r0 = smu + SK_W + d0 * 64;
            const uint32_t* r1 = smu + SK_W + (d0 + 4) * 64;
            uint4 k00 = *(const uint4*)(r0 + off0);
            uint4 k01 = *(const uint4*)(r0 + (off0 ^ 4u));
            uint4 k10 = *(const uint4*)(r1 + off1);
            uint4 k11 = *(const uint4*)(r1 + (off1 ^ 4u));
#pragma unroll
            for (int hh = 0; hh < 2; hh++) {
                mma8(s2[hh][0], qa[hh][ks], k00.x, k10.x);
                mma8(s2[hh][1], qa[hh][ks], k00.y, k10.y);
                mma8(s2[hh][2], qa[hh][ks], k00.z, k10.z);
                mma8(s2[hh][3], qa[hh][ks], k00.w, k10.w);
                mma8(s2[hh][4], qa[hh][ks], k01.x, k11.x);
                mma8(s2[hh][5], qa[hh][ks], k01.y, k11.y);
                mma8(s2[hh][6], qa[hh][ks], k01.z, k11.z);
                mma8(s2[hh][7], qa[hh][ks], k01.w, k11.w);
            }
        }

        // ---- epilogue: leaky+exp+rowsum, P -> SMEM (tf32), conflict-free
        __syncwarp();   // prior tile's P loads done (cross-lane)
#pragma unroll
        for (int hh = 0; hh < 2; hh++) {
            uint32_t* Pb = Pw + hh * 1024;
#pragma unroll
            for (int i = 0; i < 8; i++) {
                const uint32_t col = 8u * i + 2u * tig;
                float p0 = leaky_exp(s2[hh][i][0]); ls[hh][0] += p0;
                float p1 = leaky_exp(s2[hh][i][1]); ls[hh][0] += p1;
                float p2 = leaky_exp(s2[hh][i][2]); ls[hh][1] += p2;
                float p3 = leaky_exp(s2[hh][i][3]); ls[hh][1] += p3;
                *(uint2*)(Pb + g * 64 + (col ^ swp)) = make_uint2(tf32cvt(p0), tf32cvt(p1));
                *(uint2*)(Pb + (g + 8) * 64 + (col ^ swp)) = make_uint2(tf32cvt(p2), tf32cvt(p3));
            }
        }
        __syncwarp();

        // ---- O += P V  (m32 x n64 x k64 per warp)
#pragma unroll
        for (int ks = 0; ks < 8; ks++) {
            const int k0 = ks * 8 + tig;
            const uint32_t voff0 = (8u * g) ^ ((uint32_t)(k0 & 7) << 3) ^ fixg;
            const uint32_t voff1 = (8u * g) ^ ((uint32_t)((k0 + 4) & 7) << 3) ^ fixg;
            const uint32_t* r0 = smu + SV_W + k0 * 64;
            const uint32_t* r1 = smu + SV_W + (k0 + 4) * 64;
            uint4 v00 = *(const uint4*)(r0 + voff0);
            uint4 v01 = *(const uint4*)(r0 + (voff0 ^ 4u));
            uint4 v10 = *(const uint4*)(r1 + voff1);
            uint4 v11 = *(const uint4*)(r1 + (voff1 ^ 4u));
            const uint32_t c0 = 8u * ks + tig;
#pragma unroll
            for (int hh = 0; hh < 2; hh++) {
                const uint32_t* Pb = Pw + hh * 1024;
                uint32_t pa[4];
                pa[0] = Pb[g * 64 + (c0 ^ swp)];
                pa[1] = Pb[(g + 8) * 64 + (c0 ^ swp)];
                pa[2] = Pb[g * 64 + ((c0 + 4u) ^ swp)];
                pa[3] = Pb[(g + 8) * 64 + ((c0 + 4u) ^ swp)];
                mma8(o[hh][0], pa, v00.x, v10.x);
                mma8(o[hh][1], pa, v00.y, v10.y);
                mma8(o[hh][2], pa, v00.z, v10.z);
                mma8(o[hh][3], pa, v00.w, v10.w);
                mma8(o[hh][4], pa, v01.x, v11.x);
                mma8(o[hh][5], pa, v01.y, v11.y);
                mma8(o[hh][6], pa, v01.z, v11.z);
                mma8(o[hh][7], pa, v01.w, v11.w);
            }
        }
    }

    // ---- normalize + write
#pragma unroll
    for (int hh = 0; hh < 2; hh++) {
        float a = ls[hh][0], c = ls[hh][1];
        a += __shfl_xor_sync(0xffffffffu, a, 1);
        a += __shfl_xor_sync(0xffffffffu, a, 2);
        c += __shfl_xor_sync(0xffffffffu, c, 1);
        c += __shfl_xor_sync(0xffffffffu, c, 2);
        const float inv0 = 1.0f / a;
        const float inv1 = 1.0f / c;
        const int row0 = qbase + w * 32 + hh * 16 + g;
        float* p0 = out + (size_t)(b * T_LEN + row0) * IN_DIM + head * D_DIM;
        float* p1 = p0 + 8 * IN_DIM;
#pragma unroll
        for (int i = 0; i < 8; i++) {
            const int col = i * 8 + 2 * tig;
            *(float2*)(p0 + col) = make_float2(o[hh][i][0] * inv0, o[hh][i][1] * inv0);
            *(float2*)(p1 + col) = make_float2(o[hh][i][2] * inv1, o[hh][i][3] * inv1);
        }
    }
}

// ---------------------------------------------------------------------------

extern "C" void kernel_launch(void* const* d_in, const int* in_sizes, int n_in,
                              void* d_out, int out_size)
{
    const float* h = (const float*)d_in[0];
    const float* W = (const float*)d_in[1];
    float* out = (float*)d_out;

    static bool attr_set = false;
    if (!attr_set) {
        cudaFuncSetAttribute(gat_attn_mma, cudaFuncAttributeMaxDynamicSharedMemorySize, SMEM_BYTES);
        attr_set = true;
    }

    dim3 g1(IN_DIM / 64, M_TOT / 64);
    gat_gemm_kernel<<<g1, 256>>>(h, W);

    dim3 g2(T_LEN / 128, B_SZ * H_CNT);
    gat_attn_mma<<<g2, 128, SMEM_BYTES>>>(out);
}

// round 9
// speedup vs baseline: 4.0754x; 1.5666x over previous
#include <cuda_runtime.h>
#include <cuda_fp16.h>
#include <cstdint>

// GraphAttentionLayer — fp16 mma.sync flash attention, conflict-free SMEM.
//   h: (8, 2048, 256) fp32, W: (256, 256) fp32
//   Wh = h @ W -> (B=8, T=2048, H=4, D=64)  [stored fp16]
//   S = (Q K^T)/8, leaky_relu(0.2), softmax over keys, O = P V  (fp32 accum)
//
// Softmax computed with a uniform shift: p = exp(y - 8) (shift cancels in the
// normalization). Keeps p within fp16 range: diagonal self-scores reach
// y ~ chi2(64)/8 <= ~15 -> exp(y) overflows fp16; exp(y-8) does not.

#define T_LEN   2048
#define B_SZ    8
#define H_CNT   4
#define D_DIM   64
#define IN_DIM  256
#define M_TOT   (B_SZ * T_LEN)

#define EXP_SHIFT 8.0f

__device__ __half g_Whh[(size_t)M_TOT * IN_DIM];   // 8 MB scratch (fp16 Wh)

// ---------------------------------------------------------------------------
__device__ __forceinline__ uint32_t packh2(float lo, float hi) {
    uint32_t d;
    asm("cvt.rn.f16x2.f32 %0, %1, %2;" : "=r"(d) : "f"(hi), "f"(lo));
    return d;
}

// D += A*B, m16n8k16, f16 in / f32 accum. A row-major (4 regs), B col-major (2).
__device__ __forceinline__ void mma16(float* c, const uint32_t* a,
                                      uint32_t b0, uint32_t b1) {
    asm volatile(
        "mma.sync.aligned.m16n8k16.row.col.f32.f16.f16.f32 "
        "{%0,%1,%2,%3}, {%4,%5,%6,%7}, {%8,%9}, {%0,%1,%2,%3};"
        : "+f"(c[0]), "+f"(c[1]), "+f"(c[2]), "+f"(c[3])
        : "r"(a[0]), "r"(a[1]), "r"(a[2]), "r"(a[3]), "r"(b0), "r"(b1));
}

__device__ __forceinline__ float leaky_exp(float x) {
    float y = x * 0.125f;
    y = (y > 0.f) ? y : 0.2f * y;
    return __expf(y - EXP_SHIFT);
}

// ---------------------------------------------------------------------------
// GEMM: Whh = fp16(h @ W)   (16384x256 * 256x256)
// ---------------------------------------------------------------------------
__global__ void __launch_bounds__(256) gat_gemm_kernel(
    const float* __restrict__ A, const float* __restrict__ B)
{
    __shared__ float4 As[16][16];
    __shared__ float4 Bs[16][16];
    const int tid = threadIdx.x;
    const int tx = tid & 15, ty = tid >> 4;
    const int rowBase = blockIdx.y * 64, colBase = blockIdx.x * 64;

    float acc[4][4];
#pragma unroll
    for (int i = 0; i < 4; i++)
#pragma unroll
        for (int j = 0; j < 4; j++) acc[i][j] = 0.f;

    for (int k0 = 0; k0 < IN_DIM; k0 += 16) {
        {
            const int m = tid >> 2, kq = tid & 3;
            float4 av = *(const float4*)(A + (size_t)(rowBase + m) * IN_DIM + k0 + kq * 4);
            float* Asf = (float*)As;
            Asf[(kq * 4 + 0) * 64 + m] = av.x;
            Asf[(kq * 4 + 1) * 64 + m] = av.y;
            Asf[(kq * 4 + 2) * 64 + m] = av.z;
            Asf[(kq * 4 + 3) * 64 + m] = av.w;
        }
        {
            const int k = tid >> 4, n4 = tid & 15;
            Bs[k][n4] = *(const float4*)(B + (size_t)(k0 + k) * IN_DIM + colBase + n4 * 4);
        }
        __syncthreads();
#pragma unroll
        for (int k = 0; k < 16; k++) {
            float4 a = As[k][ty];
            float4 b = Bs[k][tx];
            acc[0][0] += a.x*b.x; acc[0][1] += a.x*b.y; acc[0][2] += a.x*b.z; acc[0][3] += a.x*b.w;
            acc[1][0] += a.y*b.x; acc[1][1] += a.y*b.y; acc[1][2] += a.y*b.z; acc[1][3] += a.y*b.w;
            acc[2][0] += a.z*b.x; acc[2][1] += a.z*b.y; acc[2][2] += a.z*b.z; acc[2][3] += a.z*b.w;
            acc[3][0] += a.w*b.x; acc[3][1] += a.w*b.y; acc[3][2] += a.w*b.z; acc[3][3] += a.w*b.w;
        }
        __syncthreads();
    }
#pragma unroll
    for (int i = 0; i < 4; i++) {
        uint2 v = make_uint2(packh2(acc[i][0], acc[i][1]), packh2(acc[i][2], acc[i][3]));
        *(uint2*)(g_Whh + (size_t)(rowBase + ty * 4 + i) * IN_DIM + colBase + tx * 4) = v;
    }
}

// ---------------------------------------------------------------------------
// Flash attention, fp16. CTA = 128 thr (4 warps), warp = 32 queries (2x m16).
// Key-tile 64, 32 tiles. Grid (16, 32).
//
// Words are half2 pairs. P(x) = ((x&7)<<3)|(x>>3), fix(p) = (p&32)>>3.
//   Kp: word (p=d-pair, key)   at p*64  + (P(key) ^ ((p&7)<<3)  ^ fix(P(key)))
//   Vp: word (kp=key-pair, d)  at kp*64 + (P(d)   ^ ((kp&7)<<3) ^ fix(P(d)))
//   Pb: word (q, kp)           at q*32  + (kp ^ ((q&7)<<2))       [per warp]
// All fills, fragment loads, and P round-trips are bank-conflict-free.
// ---------------------------------------------------------------------------
#define SK_W  0
#define SV_W  2048
#define SP_W  4096
#define SMEM_WORDS 8192
#define SMEM_BYTES (SMEM_WORDS * 4)   // 32 KB

__global__ void __launch_bounds__(128, 2) gat_attn_mma(float* __restrict__ out)
{
    extern __shared__ uint32_t smu[];
    const int tid = threadIdx.x;
    const int w   = tid >> 5;
    const int l   = tid & 31;
    const int g   = l >> 2;
    const int tig = l & 3;

    const int bh = blockIdx.y, b = bh >> 2, head = bh & 3;
    const int qbase = blockIdx.x * 128;
    const __half* whh = g_Whh + (size_t)b * T_LEN * IN_DIM + head * D_DIM;

    // ---- Q fragments qa[half][ks][4] (packed half2 words straight from gmem)
    uint32_t qa[2][4][4];
#pragma unroll
    for (int hh = 0; hh < 2; hh++) {
        const uint32_t* q0 = (const uint32_t*)(whh + (size_t)(qbase + w * 32 + hh * 16 + g) * IN_DIM);
        const uint32_t* q1 = q0 + 8 * (IN_DIM / 2);
#pragma unroll
        for (int ks = 0; ks < 4; ks++) {
            qa[hh][ks][0] = q0[8 * ks + tig];
            qa[hh][ks][1] = q1[8 * ks + tig];
            qa[hh][ks][2] = q0[8 * ks + 4 + tig];
            qa[hh][ks][3] = q1[8 * ks + 4 + tig];
        }
    }

    float o[2][8][4];
#pragma unroll
    for (int hh = 0; hh < 2; hh++)
#pragma unroll
        for (int i = 0; i < 8; i++)
#pragma unroll
            for (int j = 0; j < 4; j++) o[hh][i][j] = 0.f;
    float ls[2][2] = {{0.f, 0.f}, {0.f, 0.f}};

    uint32_t* Pw = smu + SP_W + w * 1024;
    const uint32_t swp  = (uint32_t)g << 2;
    const uint32_t fixg = (uint32_t)(g & 4);

    // fill mappings
    const int fr = tid & 63, fh = tid >> 6;
    const uint32_t posF = (((uint32_t)fr & 7) << 3) | ((uint32_t)fr >> 3);
    const uint32_t fixF = (posF & 32) >> 3;

    for (int t = 0; t < 32; t++) {
        __syncthreads();   // previous tile fully consumed

        // ---- pass A: Kp (thread = key fr, d-half fh). Direct fp16 word copy.
        {
            const uint4* src = (const uint4*)((const uint32_t*)(whh + (size_t)(t * 64 + fr) * IN_DIM) + fh * 16);
#pragma unroll
            for (int j = 0; j < 4; j++) {
                uint4 v = src[j];
                uint32_t vv[4] = {v.x, v.y, v.z, v.w};
#pragma unroll
                for (int m = 0; m < 4; m++) {
                    const int p = fh * 16 + j * 4 + m;
                    smu[SK_W + p * 64 + (posF ^ ((uint32_t)(p & 7) << 3) ^ fixF)] = vv[m];
                }
            }
        }
        // ---- pass B: Vp (thread = d fr, key-half fh). Pack key-pairs.
        {
            const __half* s0 = whh + (size_t)(t * 64 + fh * 32) * IN_DIM + fr;
#pragma unroll
            for (int s = 0; s < 16; s++) {
                const int kp = fh * 16 + s;
                uint32_t lo = *(const unsigned short*)(s0 + (size_t)(2 * s) * IN_DIM);
                uint32_t hi = *(const unsigned short*)(s0 + (size_t)(2 * s + 1) * IN_DIM);
                smu[SV_W + kp * 64 + (posF ^ ((uint32_t)(kp & 7) << 3) ^ fixF)] = lo | (hi << 16);
            }
        }
        __syncthreads();

        // ---- S = Q K^T  (m32 x n64 x k64 per warp, 4 k16 steps)
        float s2[2][8][4];
#pragma unroll
        for (int hh = 0; hh < 2; hh++)
#pragma unroll
            for (int i = 0; i < 8; i++)
#pragma unroll
                for (int j = 0; j < 4; j++) s2[hh][i][j] = 0.f;

#pragma unroll
        for (int ks = 0; ks < 4; ks++) {
            const int p0 = 8 * ks + tig, p1 = p0 + 4;
            const uint32_t off0 = (8u * g) ^ ((uint32_t)(p0 & 7) << 3) ^ fixg;
            const uint32_t off1 = (8u * g) ^ ((uint32_t)(p1 & 7) << 3) ^ fixg;
            const uint32_t* r0 = smu + SK_W + p0 * 64;
            const uint32_t* r1 = smu + SK_W + p1 * 64;
            uint4 k00 = *(const uint4*)(r0 + off0);
            uint4 k01 = *(const uint4*)(r0 + (off0 ^ 4u));
            uint4 k10 = *(const uint4*)(r1 + off1);
            uint4 k11 = *(const uint4*)(r1 + (off1 ^ 4u));
#pragma unroll
            for (int hh = 0; hh < 2; hh++) {
                mma16(s2[hh][0], qa[hh][ks], k00.x, k10.x);
                mma16(s2[hh][1], qa[hh][ks], k00.y, k10.y);
                mma16(s2[hh][2], qa[hh][ks], k00.z, k10.z);
                mma16(s2[hh][3], qa[hh][ks], k00.w, k10.w);
                mma16(s2[hh][4], qa[hh][ks], k01.x, k11.x);
                mma16(s2[hh][5], qa[hh][ks], k01.y, k11.y);
                mma16(s2[hh][6], qa[hh][ks], k01.z, k11.z);
                mma16(s2[hh][7], qa[hh][ks], k01.w, k11.w);
            }
        }

        // ---- epilogue: leaky+exp(-shift)+rowsum, P -> SMEM (fp16 words)
        __syncwarp();   // prior tile's P loads done
#pragma unroll
        for (int hh = 0; hh < 2; hh++) {
            const int q0r = hh * 16 + g;
#pragma unroll
            for (int i = 0; i < 8; i++) {
                float p0 = leaky_exp(s2[hh][i][0]); ls[hh][0] += p0;
                float p1 = leaky_exp(s2[hh][i][1]); ls[hh][0] += p1;
                float p2 = leaky_exp(s2[hh][i][2]); ls[hh][1] += p2;
                float p3 = leaky_exp(s2[hh][i][3]); ls[hh][1] += p3;
                const uint32_t kp = 4u * i + (uint32_t)tig;
                Pw[q0r * 32 + (kp ^ swp)]       = packh2(p0, p1);
                Pw[(q0r + 8) * 32 + (kp ^ swp)] = packh2(p2, p3);
            }
        }
        __syncwarp();

        // ---- O += P V  (m32 x n64 x k64 per warp, 4 k16 steps)
#pragma unroll
        for (int ks = 0; ks < 4; ks++) {
            const int kp0 = 8 * ks + tig, kp1 = kp0 + 4;
            const uint32_t off0 = (8u * g) ^ ((uint32_t)(kp0 & 7) << 3) ^ fixg;
            const uint32_t off1 = (8u * g) ^ ((uint32_t)(kp1 & 7) << 3) ^ fixg;
            const uint32_t* r0 = smu + SV_W + kp0 * 64;
            const uint32_t* r1 = smu + SV_W + kp1 * 64;
            uint4 v00 = *(const uint4*)(r0 + off0);
            uint4 v01 = *(const uint4*)(r0 + (off0 ^ 4u));
            uint4 v10 = *(const uint4*)(r1 + off1);
            uint4 v11 = *(const uint4*)(r1 + (off1 ^ 4u));
#pragma unroll
            for (int hh = 0; hh < 2; hh++) {
                const int q0r = hh * 16 + g;
                uint32_t pa[4];
                pa[0] = Pw[q0r * 32 + ((uint32_t)kp0 ^ swp)];
                pa[1] = Pw[(q0r + 8) * 32 + ((uint32_t)kp0 ^ swp)];
                pa[2] = Pw[q0r * 32 + ((uint32_t)kp1 ^ swp)];
                pa[3] = Pw[(q0r + 8) * 32 + ((uint32_t)kp1 ^ swp)];
                mma16(o[hh][0], pa, v00.x, v10.x);
                mma16(o[hh][1], pa, v00.y, v10.y);
                mma16(o[hh][2], pa, v00.z, v10.z);
                mma16(o[hh][3], pa, v00.w, v10.w);
                mma16(o[hh][4], pa, v01.x, v11.x);
                mma16(o[hh][5], pa, v01.y, v11.y);
                mma16(o[hh][6], pa, v01.z, v11.z);
                mma16(o[hh][7], pa, v01.w, v11.w);
            }
        }
    }

    // ---- normalize + write
#pragma unroll
    for (int hh = 0; hh < 2; hh++) {
        float a = ls[hh][0], c = ls[hh][1];
        a += __shfl_xor_sync(0xffffffffu, a, 1);
        a += __shfl_xor_sync(0xffffffffu, a, 2);
        c += __shfl_xor_sync(0xffffffffu, c, 1);
        c += __shfl_xor_sync(0xffffffffu, c, 2);
        const float inv0 = 1.0f / a;
        const float inv1 = 1.0f / c;
        const int row0 = qbase + w * 32 + hh * 16 + g;
        float* p0 = out + (size_t)(b * T_LEN + row0) * IN_DIM + head * D_DIM;
        float* p1 = p0 + 8 * IN_DIM;
#pragma unroll
        for (int i = 0; i < 8; i++) {
            const int col = i * 8 + 2 * tig;
            *(float2*)(p0 + col) = make_float2(o[hh][i][0] * inv0, o[hh][i][1] * inv0);
            *(float2*)(p1 + col) = make_float2(o[hh][i][2] * inv1, o[hh][i][3] * inv1);
        }
    }
}

// ---------------------------------------------------------------------------

extern "C" void kernel_launch(void* const* d_in, const int* in_sizes, int n_in,
                              void* d_out, int out_size)
{
    const float* h = (const float*)d_in[0];
    const float* W = (const float*)d_in[1];
    float* out = (float*)d_out;

    static bool attr_set = false;
    if (!attr_set) {
        cudaFuncSetAttribute(gat_attn_mma, cudaFuncAttributeMaxDynamicSharedMemorySize, SMEM_BYTES);
        attr_set = true;
    }

    dim3 g1(IN_DIM / 64, M_TOT / 64);
    gat_gemm_kernel<<<g1, 256>>>(h, W);

    dim3 g2(T_LEN / 128, B_SZ * H_CNT);
    gat_attn_mma<<<g2, 128, SMEM_BYTES>>>(out);
}

// round 10
// speedup vs baseline: 6.1502x; 1.5091x over previous
#include <cuda_runtime.h>
#include <cuda_fp16.h>
#include <cstdint>

// GraphAttentionLayer — fp16 mma.sync flash attention.
//   Single [key][d] smem tile per key-block serves BOTH mma operand layouts via
//   ldmatrix / ldmatrix.trans; P stays in registers (S C-frag == PV A-frag);
//   cp.async double-buffered tile prefetch.
//   Softmax uses uniform shift exp(y-8) (cancels in normalization; keeps fp16 range).

#define T_LEN   2048
#define B_SZ    8
#define H_CNT   4
#define D_DIM   64
#define IN_DIM  256
#define M_TOT   (B_SZ * T_LEN)

#define EXP_SHIFT 8.0f

__device__ __half g_Whh[(size_t)M_TOT * IN_DIM];   // 8 MB scratch (fp16 Wh)

// ---------------------------------------------------------------------------
__device__ __forceinline__ uint32_t packh2(float lo, float hi) {
    uint32_t d;
    asm("cvt.rn.f16x2.f32 %0, %1, %2;" : "=r"(d) : "f"(hi), "f"(lo));
    return d;
}
__device__ __forceinline__ void mma16(float* c, const uint32_t* a,
                                      uint32_t b0, uint32_t b1) {
    asm volatile(
        "mma.sync.aligned.m16n8k16.row.col.f32.f16.f16.f32 "
        "{%0,%1,%2,%3}, {%4,%5,%6,%7}, {%8,%9}, {%0,%1,%2,%3};"
        : "+f"(c[0]), "+f"(c[1]), "+f"(c[2]), "+f"(c[3])
        : "r"(a[0]), "r"(a[1]), "r"(a[2]), "r"(a[3]), "r"(b0), "r"(b1));
}
__device__ __forceinline__ float leaky_exp(float x) {
    float y = x * 0.125f;
    y = (y > 0.f) ? y : 0.2f * y;
    return __expf(y - EXP_SHIFT);
}
__device__ __forceinline__ uint32_t smem_addr(const void* p) {
    uint32_t a;
    asm("{ .reg .u64 t; cvta.to.shared.u64 t, %1; cvt.u32.u64 %0, t; }" : "=r"(a) : "l"(p));
    return a;
}
__device__ __forceinline__ void ldsm4(uint32_t& r0, uint32_t& r1, uint32_t& r2,
                                      uint32_t& r3, uint32_t addr) {
    asm volatile("ldmatrix.sync.aligned.m8n8.x4.shared.b16 {%0,%1,%2,%3}, [%4];"
                 : "=r"(r0), "=r"(r1), "=r"(r2), "=r"(r3) : "r"(addr));
}
__device__ __forceinline__ void ldsm4t(uint32_t& r0, uint32_t& r1, uint32_t& r2,
                                       uint32_t& r3, uint32_t addr) {
    asm volatile("ldmatrix.sync.aligned.m8n8.x4.trans.shared.b16 {%0,%1,%2,%3}, [%4];"
                 : "=r"(r0), "=r"(r1), "=r"(r2), "=r"(r3) : "r"(addr));
}
#define CP_ASYNC16(dst, src) \
    asm volatile("cp.async.cg.shared.global [%0], [%1], 16;" :: "r"(dst), "l"(src) : "memory")
#define CP_COMMIT() asm volatile("cp.async.commit_group;" ::: "memory")
#define CP_WAIT1()  asm volatile("cp.async.wait_group 1;" ::: "memory")
#define CP_WAIT0()  asm volatile("cp.async.wait_group 0;" ::: "memory")

// ---------------------------------------------------------------------------
// GEMM: Whh = fp16(h @ W)   (16384x256 * 256x256), fp32 SIMT
// ---------------------------------------------------------------------------
__global__ void __launch_bounds__(256) gat_gemm_kernel(
    const float* __restrict__ A, const float* __restrict__ B)
{
    __shared__ float4 As[16][16];
    __shared__ float4 Bs[16][16];
    const int tid = threadIdx.x;
    const int tx = tid & 15, ty = tid >> 4;
    const int rowBase = blockIdx.y * 64, colBase = blockIdx.x * 64;

    float acc[4][4];
#pragma unroll
    for (int i = 0; i < 4; i++)
#pragma unroll
        for (int j = 0; j < 4; j++) acc[i][j] = 0.f;

    for (int k0 = 0; k0 < IN_DIM; k0 += 16) {
        {
            const int m = tid >> 2, kq = tid & 3;
            float4 av = *(const float4*)(A + (size_t)(rowBase + m) * IN_DIM + k0 + kq * 4);
            float* Asf = (float*)As;
            Asf[(kq * 4 + 0) * 64 + m] = av.x;
            Asf[(kq * 4 + 1) * 64 + m] = av.y;
            Asf[(kq * 4 + 2) * 64 + m] = av.z;
            Asf[(kq * 4 + 3) * 64 + m] = av.w;
        }
        {
            const int k = tid >> 4, n4 = tid & 15;
            Bs[k][n4] = *(const float4*)(B + (size_t)(k0 + k) * IN_DIM + colBase + n4 * 4);
        }
        __syncthreads();
#pragma unroll
        for (int k = 0; k < 16; k++) {
            float4 a = As[k][ty];
            float4 b = Bs[k][tx];
            acc[0][0] += a.x*b.x; acc[0][1] += a.x*b.y; acc[0][2] += a.x*b.z; acc[0][3] += a.x*b.w;
            acc[1][0] += a.y*b.x; acc[1][1] += a.y*b.y; acc[1][2] += a.y*b.z; acc[1][3] += a.y*b.w;
            acc[2][0] += a.z*b.x; acc[2][1] += a.z*b.y; acc[2][2] += a.z*b.z; acc[2][3] += a.z*b.w;
            acc[3][0] += a.w*b.x; acc[3][1] += a.w*b.y; acc[3][2] += a.w*b.z; acc[3][3] += a.w*b.w;
        }
        __syncthreads();
    }
#pragma unroll
    for (int i = 0; i < 4; i++) {
        uint2 v = make_uint2(packh2(acc[i][0], acc[i][1]), packh2(acc[i][2], acc[i][3]));
        *(uint2*)(g_Whh + (size_t)(rowBase + ty * 4 + i) * IN_DIM + colBase + tx * 4) = v;
    }
}

// ---------------------------------------------------------------------------
// Flash attention. CTA = 128 thr (4 warps), warp = 32 queries (2x m16).
// Key-tile 64, 32 tiles, double-buffered cp.async prefetch.
//
// Tile layout (fp16): row = key (64 rows x 128B), 16B chunk c of row r stored
// at chunk (c ^ (r & 7)). ldmatrix rows = 8 consecutive keys at a fixed chunk
// -> 8 distinct chunk slots -> conflict-free.
// ---------------------------------------------------------------------------
#define BUF_BYTES 8192

__global__ void __launch_bounds__(128, 2) gat_attn_mma(float* __restrict__ out)
{
    __shared__ uint32_t smu[2 * BUF_BYTES / 4];   // 16 KB

    const int tid = threadIdx.x;
    const int w   = tid >> 5;
    const int l   = tid & 31;
    const int g   = l >> 2;
    const int tig = l & 3;

    const int bh = blockIdx.y, b = bh >> 2, head = bh & 3;
    const int qbase = blockIdx.x * 128;
    const __half* whh = g_Whh + (size_t)b * T_LEN * IN_DIM + head * D_DIM;

    const uint32_t smbase = smem_addr(smu);

    // ---- fill setup (thread = half-row): 4 x cp.async 16B per tile
    const int frow = tid >> 1, fhf = tid & 1;
    const char* fsrc0 = (const char*)(whh + (size_t)frow * IN_DIM + fhf * 32);
    uint32_t fdst[4];
#pragma unroll
    for (int j = 0; j < 4; j++) {
        const int c = fhf * 4 + j;
        fdst[j] = smbase + (uint32_t)(frow * 128 + ((c ^ (frow & 7)) << 4));
    }

    // ---- prefetch tile 0, overlap with Q-frag loads
    {
        const char* s = fsrc0;
#pragma unroll
        for (int j = 0; j < 4; j++) CP_ASYNC16(fdst[j], s + 16 * j);
        CP_COMMIT();
    }

    // ---- Q fragments qa[half][ks][4] (packed half2 words from gmem)
    uint32_t qa[2][4][4];
#pragma unroll
    for (int hh = 0; hh < 2; hh++) {
        const uint32_t* q0 = (const uint32_t*)(whh + (size_t)(qbase + w * 32 + hh * 16 + g) * IN_DIM);
        const uint32_t* q1 = q0 + 8 * (IN_DIM / 2);
#pragma unroll
        for (int ks = 0; ks < 4; ks++) {
            qa[hh][ks][0] = q0[8 * ks + tig];
            qa[hh][ks][1] = q1[8 * ks + tig];
            qa[hh][ks][2] = q0[8 * ks + 4 + tig];
            qa[hh][ks][3] = q1[8 * ks + 4 + tig];
        }
    }

    float o[2][8][4];
#pragma unroll
    for (int hh = 0; hh < 2; hh++)
#pragma unroll
        for (int i = 0; i < 8; i++)
#pragma unroll
            for (int j = 0; j < 4; j++) o[hh][i][j] = 0.f;
    float ls[2][2] = {{0.f, 0.f}, {0.f, 0.f}};

    // ldmatrix lane-address components
    const uint32_t lk7  = (uint32_t)(l & 7);
    const int sKey = ((l >> 4) << 3) + (l & 7);          // + 16*i
    const uint32_t sSeg = (uint32_t)((l >> 3) & 1);
    const int vKey = (((l >> 3) & 1) << 3) + (l & 7);    // + 16*ks
    const uint32_t vJ  = (uint32_t)(l >> 4);             // + 2*i

    for (int t = 0; t < 32; t++) {
        if (t < 31) {
            const uint32_t bofs = (uint32_t)(((t + 1) & 1) * BUF_BYTES);
            const char* s = fsrc0 + (size_t)(t + 1) * 64 * IN_DIM * sizeof(__half);
#pragma unroll
            for (int j = 0; j < 4; j++) CP_ASYNC16(fdst[j] + bofs, s + 16 * j);
            CP_COMMIT();
            CP_WAIT1();
        } else {
            CP_WAIT0();
        }
        __syncthreads();

        const uint32_t bb = smbase + (uint32_t)((t & 1) * BUF_BYTES);

        // ---- S = Q K^T  (m32 x n64 x k64 per warp)
        float s2[2][8][4];
#pragma unroll
        for (int hh = 0; hh < 2; hh++)
#pragma unroll
            for (int i = 0; i < 8; i++)
#pragma unroll
                for (int j = 0; j < 4; j++) s2[hh][i][j] = 0.f;

#pragma unroll
        for (int ks = 0; ks < 4; ks++) {
#pragma unroll
            for (int i = 0; i < 4; i++) {
                uint32_t r0, r1, r2, r3;
                const uint32_t addr = bb + (uint32_t)((16 * i + sKey) * 128
                                       + ((((uint32_t)(2 * ks) + sSeg) ^ lk7) << 4));
                ldsm4(r0, r1, r2, r3, addr);
#pragma unroll
                for (int hh = 0; hh < 2; hh++) {
                    mma16(s2[hh][2 * i],     qa[hh][ks], r0, r1);
                    mma16(s2[hh][2 * i + 1], qa[hh][ks], r2, r3);
                }
            }
        }

        // ---- epilogue: leaky+exp(-shift)+rowsum; P packed into registers.
        // C-frag (g, 8j+2tig..+1 / g+8, ...) == A-frag layout for PV.
        uint32_t ph[2][8][2];
#pragma unroll
        for (int hh = 0; hh < 2; hh++) {
#pragma unroll
            for (int j = 0; j < 8; j++) {
                float p0 = leaky_exp(s2[hh][j][0]);
                float p1 = leaky_exp(s2[hh][j][1]);
                float p2 = leaky_exp(s2[hh][j][2]);
                float p3 = leaky_exp(s2[hh][j][3]);
                ls[hh][0] += p0 + p1;
                ls[hh][1] += p2 + p3;
                ph[hh][j][0] = packh2(p0, p1);
                ph[hh][j][1] = packh2(p2, p3);
            }
        }

        // ---- O += P V  (m32 x n64 x k64 per warp; B via ldmatrix.trans)
#pragma unroll
        for (int ks = 0; ks < 4; ks++) {
#pragma unroll
            for (int i = 0; i < 4; i++) {
                uint32_t r0, r1, r2, r3;
                const uint32_t addr = bb + (uint32_t)((16 * ks + vKey) * 128
                                       + ((((uint32_t)(2 * i) + vJ) ^ lk7) << 4));
                ldsm4t(r0, r1, r2, r3, addr);
#pragma unroll
                for (int hh = 0; hh < 2; hh++) {
                    uint32_t pa[4] = { ph[hh][2 * ks][0],     ph[hh][2 * ks][1],
                                       ph[hh][2 * ks + 1][0], ph[hh][2 * ks + 1][1] };
                    mma16(o[hh][2 * i],     pa, r0, r1);
                    mma16(o[hh][2 * i + 1], pa, r2, r3);
                }
            }
        }
        __syncthreads();
    }

    // ---- normalize + write
#pragma unroll
    for (int hh = 0; hh < 2; hh++) {
        float a = ls[hh][0], c = ls[hh][1];
        a += __shfl_xor_sync(0xffffffffu, a, 1);
        a += __shfl_xor_sync(0xffffffffu, a, 2);
        c += __shfl_xor_sync(0xffffffffu, c, 1);
        c += __shfl_xor_sync(0xffffffffu, c, 2);
        const float inv0 = 1.0f / a;
        const float inv1 = 1.0f / c;
        const int row0 = qbase + w * 32 + hh * 16 + g;
        float* p0 = out + (size_t)(b * T_LEN + row0) * IN_DIM + head * D_DIM;
        float* p1 = p0 + 8 * IN_DIM;
#pragma unroll
        for (int i = 0; i < 8; i++) {
            const int col = i * 8 + 2 * tig;
            *(float2*)(p0 + col) = make_float2(o[hh][i][0] * inv0, o[hh][i][1] * inv0);
            *(float2*)(p1 + col) = make_float2(o[hh][i][2] * inv1, o[hh][i][3] * inv1);
        }
    }
}

// ---------------------------------------------------------------------------

extern "C" void kernel_launch(void* const* d_in, const int* in_sizes, int n_in,
                              void* d_out, int out_size)
{
    const float* h = (const float*)d_in[0];
    const float* W = (const float*)d_in[1];
    float* out = (float*)d_out;

    dim3 g1(IN_DIM / 64, M_TOT / 64);
    gat_gemm_kernel<<<g1, 256>>>(h, W);

    dim3 g2(T_LEN / 128, B_SZ * H_CNT);
    gat_attn_mma<<<g2, 128>>>(out);
}

// round 12
// speedup vs baseline: 7.8570x; 1.2775x over previous
#include <cuda_runtime.h>
#include <cuda_fp16.h>
#include <cstdint>

// GraphAttentionLayer — all-tensor-core pipeline.
//   conv:  g_hh = fp16(h), g_W16 = fp16(W)
//   gemm:  g_Whh = fp16(g_hh @ g_W16)      (mma.sync fp16, fp32 accum)
//   attn:  flash attention (mma.sync fp16, ldmatrix single-tile, P in regs,
//          cp.async double buffer, exp(y-8) shift softmax)

#define T_LEN   2048
#define B_SZ    8
#define H_CNT   4
#define D_DIM   64
#define IN_DIM  256
#define M_TOT   (B_SZ * T_LEN)

#define EXP_SHIFT 8.0f

__device__ __half g_hh [(size_t)M_TOT * IN_DIM];   // 8 MB   fp16 h
__device__ __half g_W16[(size_t)IN_DIM * IN_DIM];  // 128 KB fp16 W
__device__ __half g_Whh[(size_t)M_TOT * IN_DIM];   // 8 MB   fp16 Wh

// ---------------------------------------------------------------------------
__device__ __forceinline__ uint32_t packh2(float lo, float hi) {
    uint32_t d;
    asm("cvt.rn.f16x2.f32 %0, %1, %2;" : "=r"(d) : "f"(hi), "f"(lo));
    return d;
}
__device__ __forceinline__ void mma16(float* c, const uint32_t* a,
                                      uint32_t b0, uint32_t b1) {
    asm volatile(
        "mma.sync.aligned.m16n8k16.row.col.f32.f16.f16.f32 "
        "{%0,%1,%2,%3}, {%4,%5,%6,%7}, {%8,%9}, {%0,%1,%2,%3};"
        : "+f"(c[0]), "+f"(c[1]), "+f"(c[2]), "+f"(c[3])
        : "r"(a[0]), "r"(a[1]), "r"(a[2]), "r"(a[3]), "r"(b0), "r"(b1));
}
__device__ __forceinline__ float leaky_exp(float x) {
    float y = x * 0.125f;
    y = (y > 0.f) ? y : 0.2f * y;
    return __expf(y - EXP_SHIFT);
}
__device__ __forceinline__ uint32_t smem_addr(const void* p) {
    uint32_t a;
    asm("{ .reg .u64 t; cvta.to.shared.u64 t, %1; cvt.u32.u64 %0, t; }" : "=r"(a) : "l"(p));
    return a;
}
__device__ __forceinline__ void ldsm4(uint32_t& r0, uint32_t& r1, uint32_t& r2,
                                      uint32_t& r3, uint32_t addr) {
    asm volatile("ldmatrix.sync.aligned.m8n8.x4.shared.b16 {%0,%1,%2,%3}, [%4];"
                 : "=r"(r0), "=r"(r1), "=r"(r2), "=r"(r3) : "r"(addr));
}
__device__ __forceinline__ void ldsm4t(uint32_t& r0, uint32_t& r1, uint32_t& r2,
                                       uint32_t& r3, uint32_t addr) {
    asm volatile("ldmatrix.sync.aligned.m8n8.x4.trans.shared.b16 {%0,%1,%2,%3}, [%4];"
                 : "=r"(r0), "=r"(r1), "=r"(r2), "=r"(r3) : "r"(addr));
}
#define CP_ASYNC16(dst, src) \
    asm volatile("cp.async.cg.shared.global [%0], [%1], 16;" :: "r"(dst), "l"(src) : "memory")
#define CP_COMMIT() asm volatile("cp.async.commit_group;" ::: "memory")
#define CP_WAIT1()  asm volatile("cp.async.wait_group 1;" ::: "memory")
#define CP_WAIT0()  asm volatile("cp.async.wait_group 0;" ::: "memory")

// ---------------------------------------------------------------------------
// conv: fp32 -> fp16 for h and W
// ---------------------------------------------------------------------------
#define H4  ((M_TOT * IN_DIM) / 4)        // 1048576
#define W4  ((IN_DIM * IN_DIM) / 4)       // 16384

__global__ void __launch_bounds__(256) gat_conv_kernel(
    const float4* __restrict__ h4, const float4* __restrict__ w4)
{
    const int i = blockIdx.x * 256 + threadIdx.x;
    if (i < H4) {
        float4 v = h4[i];
        ((uint2*)g_hh)[i] = make_uint2(packh2(v.x, v.y), packh2(v.z, v.w));
    } else if (i < H4 + W4) {
        const int j = i - H4;
        float4 v = w4[j];
        ((uint2*)g_W16)[j] = make_uint2(packh2(v.x, v.y), packh2(v.z, v.w));
    }
}

// ---------------------------------------------------------------------------
// Tensor GEMM: g_Whh[16384,256] = g_hh[16384,256] @ g_W16[256,256]
// Grid (128, 4), 128 thr (4 warps). CTA tile M=128, N=64, full K=256.
// W column-tile (256 x 64 fp16 = 32 KB) resident in SMEM, same swizzle +
// ldmatrix.trans addressing as the attention PV path. A-frags from gmem,
// one-step register double buffer.
// ---------------------------------------------------------------------------
__global__ void __launch_bounds__(128) gat_gemm_tc()
{
    __shared__ uint32_t smw[8192];   // 32 KB
    const int tid = threadIdx.x;
    const int w   = tid >> 5;
    const int l   = tid & 31;
    const int g   = l >> 2;
    const int tig = l & 3;
    const int m0  = blockIdx.x * 128;
    const int n0  = blockIdx.y * 64;

    const uint32_t smbase = smem_addr(smw);

    // fill W tile: 256 rows (k) x 128 B (n64 fp16), chunk c of row r at c^(r&7)
#pragma unroll
    for (int rr = 0; rr < 2; rr++) {
        const int r = tid + 128 * rr;
        const char* src = (const char*)(g_W16 + (size_t)r * IN_DIM + n0);
#pragma unroll
        for (int c = 0; c < 8; c++)
            CP_ASYNC16(smbase + (uint32_t)(r * 128 + (((uint32_t)c ^ (r & 7)) << 4)),
                       src + 16 * c);
    }
    CP_COMMIT();
    CP_WAIT0();
    __syncthreads();

    float o[2][8][4];
#pragma unroll
    for (int hh = 0; hh < 2; hh++)
#pragma unroll
        for (int i = 0; i < 8; i++)
#pragma unroll
            for (int j = 0; j < 4; j++) o[hh][i][j] = 0.f;

    const uint32_t* A0 = (const uint32_t*)(g_hh + (size_t)(m0 + w * 32 + g) * IN_DIM);
    // row strides in uint32 words: +8 rows = 1024, +16 rows (hh) = 2048

    const uint32_t lk7  = (uint32_t)(l & 7);
    const int vKey = (((l >> 3) & 1) << 3) + (l & 7);
    const uint32_t vJ = (uint32_t)(l >> 4);

    uint32_t qa[2][4], qb[2][4];
#pragma unroll
    for (int hh = 0; hh < 2; hh++) {
        const uint32_t* r0 = A0 + hh * 2048;
        qa[hh][0] = r0[tig];
        qa[hh][1] = r0[1024 + tig];
        qa[hh][2] = r0[4 + tig];
        qa[hh][3] = r0[1024 + 4 + tig];
    }

#pragma unroll
    for (int ks = 0; ks < 16; ks++) {
        uint32_t (*cur)[4] = (ks & 1) ? qb : qa;
        uint32_t (*nxt)[4] = (ks & 1) ? qa : qb;
        if (ks < 15) {
#pragma unroll
            for (int hh = 0; hh < 2; hh++) {
                const uint32_t* r0 = A0 + hh * 2048 + 8 * (ks + 1);
                nxt[hh][0] = r0[tig];
                nxt[hh][1] = r0[1024 + tig];
                nxt[hh][2] = r0[4 + tig];
                nxt[hh][3] = r0[1024 + 4 + tig];
            }
        }
#pragma unroll
        for (int i = 0; i < 4; i++) {
            uint32_t r0, r1, r2, r3;
            const uint32_t addr = smbase + (uint32_t)((16 * ks + vKey) * 128
                                   + ((((uint32_t)(2 * i) + vJ) ^ lk7) << 4));
            ldsm4t(r0, r1, r2, r3, addr);
#pragma unroll
            for (int hh = 0; hh < 2; hh++) {
                mma16(o[hh][2 * i],     cur[hh], r0, r1);
                mma16(o[hh][2 * i + 1], cur[hh], r2, r3);
            }
        }
    }

    // write C fragments (same layout as attention out-write)
#pragma unroll
    for (int hh = 0; hh < 2; hh++) {
        const int row0 = m0 + w * 32 + hh * 16 + g;
        __half* p0 = g_Whh + (size_t)row0 * IN_DIM + n0;
        __half* p1 = p0 + 8 * IN_DIM;
#pragma unroll
        for (int j = 0; j < 8; j++) {
            const int col = 8 * j + 2 * tig;
            *(uint32_t*)(p0 + col) = packh2(o[hh][j][0], o[hh][j][1]);
            *(uint32_t*)(p1 + col) = packh2(o[hh][j][2], o[hh][j][3]);
        }
    }
}

// ---------------------------------------------------------------------------
// Flash attention (unchanged from R9). CTA = 128 thr (4 warps), warp = m32.
// Key-tile 64, 32 tiles, double-buffered cp.async prefetch.
// Tile: row = key (64 x 128B), chunk c of row r at (c ^ (r & 7)).
// ---------------------------------------------------------------------------
#define BUF_BYTES 8192

__global__ void __launch_bounds__(128, 2) gat_attn_mma(float* __restrict__ out)
{
    __shared__ uint32_t smu[2 * BUF_BYTES / 4];   // 16 KB

    const int tid = threadIdx.x;
    const int w   = tid >> 5;
    const int l   = tid & 31;
    const int g   = l >> 2;
    const int tig = l & 3;

    const int bh = blockIdx.y, b = bh >> 2, head = bh & 3;
    const int qbase = blockIdx.x * 128;
    const __half* whh = g_Whh + (size_t)b * T_LEN * IN_DIM + head * D_DIM;

    const uint32_t smbase = smem_addr(smu);

    // fill setup (thread = half-row): 4 x cp.async 16B per tile
    const int frow = tid >> 1, fhf = tid & 1;
    const char* fsrc0 = (const char*)(whh + (size_t)frow * IN_DIM + fhf * 32);
    uint32_t fdst[4];
#pragma unroll
    for (int j = 0; j < 4; j++) {
        const int c = fhf * 4 + j;
        fdst[j] = smbase + (uint32_t)(frow * 128 + ((c ^ (frow & 7)) << 4));
    }

    {
        const char* s = fsrc0;
#pragma unroll
        for (int j = 0; j < 4; j++) CP_ASYNC16(fdst[j], s + 16 * j);
        CP_COMMIT();
    }

    // Q fragments
    uint32_t qa[2][4][4];
#pragma unroll
    for (int hh = 0; hh < 2; hh++) {
        const uint32_t* q0 = (const uint32_t*)(whh + (size_t)(qbase + w * 32 + hh * 16 + g) * IN_DIM);
        const uint32_t* q1 = q0 + 8 * (IN_DIM / 2);
#pragma unroll
        for (int ks = 0; ks < 4; ks++) {
            qa[hh][ks][0] = q0[8 * ks + tig];
            qa[hh][ks][1] = q1[8 * ks + tig];
            qa[hh][ks][2] = q0[8 * ks + 4 + tig];
            qa[hh][ks][3] = q1[8 * ks + 4 + tig];
        }
    }

    float o[2][8][4];
#pragma unroll
    for (int hh = 0; hh < 2; hh++)
#pragma unroll
        for (int i = 0; i < 8; i++)
#pragma unroll
            for (int j = 0; j < 4; j++) o[hh][i][j] = 0.f;
    float ls[2][2] = {{0.f, 0.f}, {0.f, 0.f}};

    const uint32_t lk7  = (uint32_t)(l & 7);
    const int sKey = ((l >> 4) << 3) + (l & 7);
    const uint32_t sSeg = (uint32_t)((l >> 3) & 1);
    const int vKey = (((l >> 3) & 1) << 3) + (l & 7);
    const uint32_t vJ  = (uint32_t)(l >> 4);

    for (int t = 0; t < 32; t++) {
        if (t < 31) {
            const uint32_t bofs = (uint32_t)(((t + 1) & 1) * BUF_BYTES);
            const char* s = fsrc0 + (size_t)(t + 1) * 64 * IN_DIM * sizeof(__half);
#pragma unroll
            for (int j = 0; j < 4; j++) CP_ASYNC16(fdst[j] + bofs, s + 16 * j);
            CP_COMMIT();
            CP_WAIT1();
        } else {
            CP_WAIT0();
        }
        __syncthreads();

        const uint32_t bb = smbase + (uint32_t)((t & 1) * BUF_BYTES);

        // S = Q K^T
        float s2[2][8][4];
#pragma unroll
        for (int hh = 0; hh < 2; hh++)
#pragma unroll
            for (int i = 0; i < 8; i++)
#pragma unroll
                for (int j = 0; j < 4; j++) s2[hh][i][j] = 0.f;

#pragma unroll
        for (int ks = 0; ks < 4; ks++) {
#pragma unroll
            for (int i = 0; i < 4; i++) {
                uint32_t r0, r1, r2, r3;
                const uint32_t addr = bb + (uint32_t)((16 * i + sKey) * 128
                                       + ((((uint32_t)(2 * ks) + sSeg) ^ lk7) << 4));
                ldsm4(r0, r1, r2, r3, addr);
#pragma unroll
                for (int hh = 0; hh < 2; hh++) {
                    mma16(s2[hh][2 * i],     qa[hh][ks], r0, r1);
                    mma16(s2[hh][2 * i + 1], qa[hh][ks], r2, r3);
                }
            }
        }

        // epilogue: leaky+exp(-shift)+rowsum; P packed into registers
        uint32_t ph[2][8][2];
#pragma unroll
        for (int hh = 0; hh < 2; hh++) {
#pragma unroll
            for (int j = 0; j < 8; j++) {
                float p0 = leaky_exp(s2[hh][j][0]);
                float p1 = leaky_exp(s2[hh][j][1]);
                float p2 = leaky_exp(s2[hh][j][2]);
                float p3 = leaky_exp(s2[hh][j][3]);
                ls[hh][0] += p0 + p1;
                ls[hh][1] += p2 + p3;
                ph[hh][j][0] = packh2(p0, p1);
                ph[hh][j][1] = packh2(p2, p3);
            }
        }

        // O += P V
#pragma unroll
        for (int ks = 0; ks < 4; ks++) {
#pragma unroll
            for (int i = 0; i < 4; i++) {
                uint32_t r0, r1, r2, r3;
                const uint32_t addr = bb + (uint32_t)((16 * ks + vKey) * 128
                                       + ((((uint32_t)(2 * i) + vJ) ^ lk7) << 4));
                ldsm4t(r0, r1, r2, r3, addr);
#pragma unroll
                for (int hh = 0; hh < 2; hh++) {
                    uint32_t pa[4] = { ph[hh][2 * ks][0],     ph[hh][2 * ks][1],
                                       ph[hh][2 * ks + 1][0], ph[hh][2 * ks + 1][1] };
                    mma16(o[hh][2 * i],     pa, r0, r1);
                    mma16(o[hh][2 * i + 1], pa, r2, r3);
                }
            }
        }
        __syncthreads();
    }

    // normalize + write
#pragma unroll
    for (int hh = 0; hh < 2; hh++) {
        float a = ls[hh][0], c = ls[hh][1];
        a += __shfl_xor_sync(0xffffffffu, a, 1);
        a += __shfl_xor_sync(0xffffffffu, a, 2);
        c += __shfl_xor_sync(0xffffffffu, c, 1);
        c += __shfl_xor_sync(0xffffffffu, c, 2);
        const float inv0 = 1.0f / a;
        const float inv1 = 1.0f / c;
        const int row0 = qbase + w * 32 + hh * 16 + g;
        float* p0 = out + (size_t)(b * T_LEN + row0) * IN_DIM + head * D_DIM;
        float* p1 = p0 + 8 * IN_DIM;
#pragma unroll
        for (int i = 0; i < 8; i++) {
            const int col = i * 8 + 2 * tig;
            *(float2*)(p0 + col) = make_float2(o[hh][i][0] * inv0, o[hh][i][1] * inv0);
            *(float2*)(p1 + col) = make_float2(o[hh][i][2] * inv1, o[hh][i][3] * inv1);
        }
    }
}

// ---------------------------------------------------------------------------

extern "C" void kernel_launch(void* const* d_in, const int* in_sizes, int n_in,
                              void* d_out, int out_size)
{
    const float* h = (const float*)d_in[0];
    const float* W = (const float*)d_in[1];
    float* out = (float*)d_out;

    gat_conv_kernel<<<(H4 + W4 + 255) / 256, 256>>>((const float4*)h, (const float4*)W);

    dim3 gg(M_TOT / 128, IN_DIM / 64);          // (128, 4)
    gat_gemm_tc<<<gg, 128>>>();

    dim3 g2(T_LEN / 128, B_SZ * H_CNT);         // (16, 32)
    gat_attn_mma<<<g2, 128>>>(out);
}

// round 13
// speedup vs baseline: 8.2686x; 1.0524x over previous
#include <cuda_runtime.h>
#include <cuda_fp16.h>
#include <cstdint>

// GraphAttentionLayer — all-tensor-core pipeline.
//   conv:  g_hh = fp16(h), g_W16 = fp16(W)
//   gemm:  g_Whh = fp16(g_hh @ g_W16)   (mma.sync fp16, cp.async-pipelined A)
//   attn:  flash attention (mma.sync fp16, ldmatrix single-tile, P in regs,
//          triple-buffer cp.async, one barrier/tile, row-sums via ones-MMA,
//          exp(y-8) shift softmax folded to FMUL+FMNMX+FFMA+EX2)

#define T_LEN   2048
#define B_SZ    8
#define H_CNT   4
#define D_DIM   64
#define IN_DIM  256
#define M_TOT   (B_SZ * T_LEN)

#define ONES2 0x3C003C00u   // fp16x2 {1.0, 1.0}

__device__ __half g_hh [(size_t)M_TOT * IN_DIM];   // 8 MB   fp16 h
__device__ __half g_W16[(size_t)IN_DIM * IN_DIM];  // 128 KB fp16 W
__device__ __half g_Whh[(size_t)M_TOT * IN_DIM];   // 8 MB   fp16 Wh

// ---------------------------------------------------------------------------
__device__ __forceinline__ uint32_t packh2(float lo, float hi) {
    uint32_t d;
    asm("cvt.rn.f16x2.f32 %0, %1, %2;" : "=r"(d) : "f"(hi), "f"(lo));
    return d;
}
__device__ __forceinline__ void mma16(float* c, const uint32_t* a,
                                      uint32_t b0, uint32_t b1) {
    asm volatile(
        "mma.sync.aligned.m16n8k16.row.col.f32.f16.f16.f32 "
        "{%0,%1,%2,%3}, {%4,%5,%6,%7}, {%8,%9}, {%0,%1,%2,%3};"
        : "+f"(c[0]), "+f"(c[1]), "+f"(c[2]), "+f"(c[3])
        : "r"(a[0]), "r"(a[1]), "r"(a[2]), "r"(a[3]), "r"(b0), "r"(b1));
}
// leaky(s/8) - 8 in log2 domain, then EX2:
//   exp(max(s,0.2s)/8 - 8) = 2^( max(s,0.2s)*log2e/8 - 8*log2e )
__device__ __forceinline__ float lexp(float s) {
    float m = fmaxf(s, 0.2f * s);
    float t = fmaf(m, 0.18033688011112043f, -11.541560327111708f);
    float r;
    asm("ex2.approx.ftz.f32 %0, %1;" : "=f"(r) : "f"(t));
    return r;
}
__device__ __forceinline__ uint32_t smem_addr(const void* p) {
    uint32_t a;
    asm("{ .reg .u64 t; cvta.to.shared.u64 t, %1; cvt.u32.u64 %0, t; }" : "=r"(a) : "l"(p));
    return a;
}
__device__ __forceinline__ void ldsm4(uint32_t& r0, uint32_t& r1, uint32_t& r2,
                                      uint32_t& r3, uint32_t addr) {
    asm volatile("ldmatrix.sync.aligned.m8n8.x4.shared.b16 {%0,%1,%2,%3}, [%4];"
                 : "=r"(r0), "=r"(r1), "=r"(r2), "=r"(r3) : "r"(addr));
}
__device__ __forceinline__ void ldsm4t(uint32_t& r0, uint32_t& r1, uint32_t& r2,
                                       uint32_t& r3, uint32_t addr) {
    asm volatile("ldmatrix.sync.aligned.m8n8.x4.trans.shared.b16 {%0,%1,%2,%3}, [%4];"
                 : "=r"(r0), "=r"(r1), "=r"(r2), "=r"(r3) : "r"(addr));
}
#define CP_ASYNC16(dst, src) \
    asm volatile("cp.async.cg.shared.global [%0], [%1], 16;" :: "r"(dst), "l"(src) : "memory")
#define CP_COMMIT() asm volatile("cp.async.commit_group;" ::: "memory")
#define CP_WAIT1()  asm volatile("cp.async.wait_group 1;" ::: "memory")
#define CP_WAIT0()  asm volatile("cp.async.wait_group 0;" ::: "memory")

// ---------------------------------------------------------------------------
// conv: fp32 -> fp16 for h and W
// ---------------------------------------------------------------------------
#define H4  ((M_TOT * IN_DIM) / 4)        // 1048576
#define W4  ((IN_DIM * IN_DIM) / 4)       // 16384

__global__ void __launch_bounds__(256) gat_conv_kernel(
    const float4* __restrict__ h4, const float4* __restrict__ w4)
{
    const int i = blockIdx.x * 256 + threadIdx.x;
    if (i < H4) {
        float4 v = h4[i];
        ((uint2*)g_hh)[i] = make_uint2(packh2(v.x, v.y), packh2(v.z, v.w));
    } else if (i < H4 + W4) {
        const int j = i - H4;
        float4 v = w4[j];
        ((uint2*)g_W16)[j] = make_uint2(packh2(v.x, v.y), packh2(v.z, v.w));
    }
}

// ---------------------------------------------------------------------------
// Tensor GEMM: g_Whh[16384,256] = g_hh @ g_W16.  Grid (128, 4), 128 thr.
// CTA tile M=128, N=64, K=256 in 16 k16-chunks.
// W column-tile resident in smem (32 KB, chunk c of row r at c^(r&7)).
// A streamed via triple-buffered cp.async chunks (4 KB = 128 rows x 16 halves,
// 16B unit u = c*128 + r, c = k-half, r = m-row; conflict-free for ldmatrix).
// ---------------------------------------------------------------------------
#define GW_WORDS 8192
#define GA_WORDS 1024
#define GA_BYTES 4096

__global__ void __launch_bounds__(128) gat_gemm_tc()
{
    __shared__ uint32_t smw[GW_WORDS + 3 * GA_WORDS];   // 44 KB
    const int tid = threadIdx.x;
    const int w   = tid >> 5;
    const int l   = tid & 31;
    const int g   = l >> 2;
    const int tig = l & 3;
    const int m0  = blockIdx.x * 128;
    const int n0  = blockIdx.y * 64;

    const uint32_t smbase = smem_addr(smw);
    const uint32_t abase  = smbase + GW_WORDS * 4;

    // ---- W tile fill (group 0)
#pragma unroll
    for (int rr = 0; rr < 2; rr++) {
        const int r = tid + 128 * rr;
        const char* src = (const char*)(g_W16 + (size_t)r * IN_DIM + n0);
#pragma unroll
        for (int c = 0; c < 8; c++)
            CP_ASYNC16(smbase + (uint32_t)(r * 128 + (((uint32_t)c ^ (r & 7)) << 4)),
                       src + 16 * c);
    }
    CP_COMMIT();

    // ---- A chunk fill: 2 units per thread
    const int au0 = tid, au1 = tid + 128;
    const int ac0 = au0 >> 7, ar0 = au0 & 127;
    const int ac1 = au1 >> 7, ar1 = au1 & 127;
    const char* asrc0 = (const char*)(g_hh + (size_t)(m0 + ar0) * IN_DIM + ac0 * 8);
    const char* asrc1 = (const char*)(g_hh + (size_t)(m0 + ar1) * IN_DIM + ac1 * 8);

    // prologue: chunks 0, 1
#pragma unroll
    for (int k = 0; k < 2; k++) {
        const uint32_t bofs = (uint32_t)(k * GA_BYTES);
        CP_ASYNC16(abase + bofs + au0 * 16, asrc0 + (size_t)k * 32);
        CP_ASYNC16(abase + bofs + au1 * 16, asrc1 + (size_t)k * 32);
        CP_COMMIT();
    }

    float o[2][8][4];
#pragma unroll
    for (int hh = 0; hh < 2; hh++)
#pragma unroll
        for (int i = 0; i < 8; i++)
#pragma unroll
            for (int j = 0; j < 4; j++) o[hh][i][j] = 0.f;

    const uint32_t lk7  = (uint32_t)(l & 7);
    const int vKey = (((l >> 3) & 1) << 3) + (l & 7);
    const uint32_t vJ = (uint32_t)(l >> 4);
    const int aRow = w * 32 + (l & 15);
    const int aCol = l >> 4;                 // k-half select

#pragma unroll
    for (int ks = 0; ks < 16; ks++) {
        if (ks < 15) CP_WAIT1(); else CP_WAIT0();
        __syncthreads();
        if (ks <= 13) {
            const uint32_t bofs = (uint32_t)(((ks + 2) % 3) * GA_BYTES);
            CP_ASYNC16(abase + bofs + au0 * 16, asrc0 + (size_t)(ks + 2) * 32);
            CP_ASYNC16(abase + bofs + au1 * 16, asrc1 + (size_t)(ks + 2) * 32);
            CP_COMMIT();
        }

        const uint32_t ab = abase + (uint32_t)((ks % 3) * GA_BYTES);
        uint32_t aa[2][4];
#pragma unroll
        for (int hh = 0; hh < 2; hh++)
            ldsm4(aa[hh][0], aa[hh][1], aa[hh][2], aa[hh][3],
                  ab + (uint32_t)(((aCol << 7) + aRow + hh * 16) << 4));

#pragma unroll
        for (int i = 0; i < 4; i++) {
            uint32_t r0, r1, r2, r3;
            const uint32_t addr = smbase + (uint32_t)((16 * ks + vKey) * 128
                                   + ((((uint32_t)(2 * i) + vJ) ^ lk7) << 4));
            ldsm4t(r0, r1, r2, r3, addr);
#pragma unroll
            for (int hh = 0; hh < 2; hh++) {
                mma16(o[hh][2 * i],     aa[hh], r0, r1);
                mma16(o[hh][2 * i + 1], aa[hh], r2, r3);
            }
        }
        __syncthreads();
    }

    // ---- write C fragments (fp16)
#pragma unroll
    for (int hh = 0; hh < 2; hh++) {
        const int row0 = m0 + w * 32 + hh * 16 + g;
        __half* p0 = g_Whh + (size_t)row0 * IN_DIM + n0;
        __half* p1 = p0 + 8 * IN_DIM;
#pragma unroll
        for (int j = 0; j < 8; j++) {
            const int col = 8 * j + 2 * tig;
            *(uint32_t*)(p0 + col) = packh2(o[hh][j][0], o[hh][j][1]);
            *(uint32_t*)(p1 + col) = packh2(o[hh][j][2], o[hh][j][3]);
        }
    }
}

// ---------------------------------------------------------------------------
// Flash attention. CTA = 128 thr (4 warps), warp = m32 (2x m16).
// Key-tile 64, 32 tiles, TRIPLE-buffered cp.async, ONE barrier per tile.
// Tile: row = key (64 x 128B), chunk c of row r at (c ^ (r & 7)).
// Row-sums accumulate in an extra ones-column MMA (fp32, across all tiles).
// ---------------------------------------------------------------------------
#define BUF_BYTES 8192

__global__ void __launch_bounds__(128, 2) gat_attn_mma(float* __restrict__ out)
{
    __shared__ uint32_t smu[3 * BUF_BYTES / 4];   // 24 KB

    const int tid = threadIdx.x;
    const int w   = tid >> 5;
    const int l   = tid & 31;
    const int g   = l >> 2;
    const int tig = l & 3;

    const int bh = blockIdx.y, b = bh >> 2, head = bh & 3;
    const int qbase = blockIdx.x * 128;
    const __half* whh = g_Whh + (size_t)b * T_LEN * IN_DIM + head * D_DIM;

    const uint32_t smbase = smem_addr(smu);

    // fill setup (thread = half-row): 4 x cp.async 16B per tile
    const int frow = tid >> 1, fhf = tid & 1;
    const char* fsrc0 = (const char*)(whh + (size_t)frow * IN_DIM + fhf * 32);
    uint32_t fdst[4];
#pragma unroll
    for (int j = 0; j < 4; j++) {
        const int c = fhf * 4 + j;
        fdst[j] = smbase + (uint32_t)(frow * 128 + ((c ^ (frow & 7)) << 4));
    }

    // prologue: prefetch tiles 0 and 1
#pragma unroll
    for (int k = 0; k < 2; k++) {
        const char* s = fsrc0 + (size_t)k * 64 * IN_DIM * sizeof(__half);
        const uint32_t bofs = (uint32_t)(k * BUF_BYTES);
#pragma unroll
        for (int j = 0; j < 4; j++) CP_ASYNC16(fdst[j] + bofs, s + 16 * j);
        CP_COMMIT();
    }

    // Q fragments
    uint32_t qa[2][4][4];
#pragma unroll
    for (int hh = 0; hh < 2; hh++) {
        const uint32_t* q0 = (const uint32_t*)(whh + (size_t)(qbase + w * 32 + hh * 16 + g) * IN_DIM);
        const uint32_t* q1 = q0 + 8 * (IN_DIM / 2);
#pragma unroll
        for (int ks = 0; ks < 4; ks++) {
            qa[hh][ks][0] = q0[8 * ks + tig];
            qa[hh][ks][1] = q1[8 * ks + tig];
            qa[hh][ks][2] = q0[8 * ks + 4 + tig];
            qa[hh][ks][3] = q1[8 * ks + 4 + tig];
        }
    }

    float o[2][8][4];
#pragma unroll
    for (int hh = 0; hh < 2; hh++)
#pragma unroll
        for (int i = 0; i < 8; i++)
#pragma unroll
            for (int j = 0; j < 4; j++) o[hh][i][j] = 0.f;
    float lsacc[2][4] = {{0.f, 0.f, 0.f, 0.f}, {0.f, 0.f, 0.f, 0.f}};

    const uint32_t lk7  = (uint32_t)(l & 7);
    const int sKey = ((l >> 4) << 3) + (l & 7);
    const uint32_t sSeg = (uint32_t)((l >> 3) & 1);
    const int vKey = (((l >> 3) & 1) << 3) + (l & 7);
    const uint32_t vJ  = (uint32_t)(l >> 4);

    for (int t = 0; t < 32; t++) {
        if (t < 31) CP_WAIT1(); else CP_WAIT0();
        __syncthreads();
        // prefetch AFTER the barrier: buffer (t+2)%3 was last read at iter t-1,
        // and every warp finished iter t-1 before this barrier released.
        if (t <= 29) {
            const uint32_t bofs = (uint32_t)(((t + 2) % 3) * BUF_BYTES);
            const char* s = fsrc0 + (size_t)(t + 2) * 64 * IN_DIM * sizeof(__half);
#pragma unroll
            for (int j = 0; j < 4; j++) CP_ASYNC16(fdst[j] + bofs, s + 16 * j);
            CP_COMMIT();
        }

        const uint32_t bb = smbase + (uint32_t)((t % 3) * BUF_BYTES);

        // ---- S = Q K^T
        float s2[2][8][4];
#pragma unroll
        for (int hh = 0; hh < 2; hh++)
#pragma unroll
            for (int i = 0; i < 8; i++)
#pragma unroll
                for (int j = 0; j < 4; j++) s2[hh][i][j] = 0.f;

#pragma unroll
        for (int ks = 0; ks < 4; ks++) {
#pragma unroll
            for (int i = 0; i < 4; i++) {
                uint32_t r0, r1, r2, r3;
                const uint32_t addr = bb + (uint32_t)((16 * i + sKey) * 128
                                       + ((((uint32_t)(2 * ks) + sSeg) ^ lk7) << 4));
                ldsm4(r0, r1, r2, r3, addr);
#pragma unroll
                for (int hh = 0; hh < 2; hh++) {
                    mma16(s2[hh][2 * i],     qa[hh][ks], r0, r1);
                    mma16(s2[hh][2 * i + 1], qa[hh][ks], r2, r3);
                }
            }
        }

        // ---- epilogue: folded leaky+exp; P packed into registers (no sums here)
        uint32_t ph[2][8][2];
#pragma unroll
        for (int hh = 0; hh < 2; hh++) {
#pragma unroll
            for (int j = 0; j < 8; j++) {
                float p0 = lexp(s2[hh][j][0]);
                float p1 = lexp(s2[hh][j][1]);
                float p2 = lexp(s2[hh][j][2]);
                float p3 = lexp(s2[hh][j][3]);
                ph[hh][j][0] = packh2(p0, p1);
                ph[hh][j][1] = packh2(p2, p3);
            }
        }

        // ---- O += P V ; row-sums += P * ones
#pragma unroll
        for (int ks = 0; ks < 4; ks++) {
            uint32_t pa[2][4];
#pragma unroll
            for (int hh = 0; hh < 2; hh++) {
                pa[hh][0] = ph[hh][2 * ks][0];
                pa[hh][1] = ph[hh][2 * ks][1];
                pa[hh][2] = ph[hh][2 * ks + 1][0];
                pa[hh][3] = ph[hh][2 * ks + 1][1];
            }
#pragma unroll
            for (int i = 0; i < 4; i++) {
                uint32_t r0, r1, r2, r3;
                const uint32_t addr = bb + (uint32_t)((16 * ks + vKey) * 128
                                       + ((((uint32_t)(2 * i) + vJ) ^ lk7) << 4));
                ldsm4t(r0, r1, r2, r3, addr);
#pragma unroll
                for (int hh = 0; hh < 2; hh++) {
                    mma16(o[hh][2 * i],     pa[hh], r0, r1);
                    mma16(o[hh][2 * i + 1], pa[hh], r2, r3);
                }
            }
            mma16(lsacc[0], pa[0], ONES2, ONES2);
            mma16(lsacc[1], pa[1], ONES2, ONES2);
        }
    }

    // ---- normalize + write (lsacc cols are identical; c0 = row g, c2 = row g+8)
#pragma unroll
    for (int hh = 0; hh < 2; hh++) {
        const float inv0 = 1.0f / lsacc[hh][0];
        const float inv1 = 1.0f / lsacc[hh][2];
        const int row0 = qbase + w * 32 + hh * 16 + g;
        float* p0 = out + (size_t)(b * T_LEN + row0) * IN_DIM + head * D_DIM;
        float* p1 = p0 + 8 * IN_DIM;
#pragma unroll
        for (int i = 0; i < 8; i++) {
            const int col = i * 8 + 2 * tig;
            *(float2*)(p0 + col) = make_float2(o[hh][i][0] * inv0, o[hh][i][1] * inv0);
            *(float2*)(p1 + col) = make_float2(o[hh][i][2] * inv1, o[hh][i][3] * inv1);
        }
    }
}

// ---------------------------------------------------------------------------

extern "C" void kernel_launch(void* const* d_in, const int* in_sizes, int n_in,
                              void* d_out, int out_size)
{
    const float* h = (const float*)d_in[0];
    const float* W = (const float*)d_in[1];
    float* out = (float*)d_out;

    gat_conv_kernel<<<(H4 + W4 + 255) / 256, 256>>>((const float4*)h, (const float4*)W);

    dim3 gg(M_TOT / 128, IN_DIM / 64);          // (128, 4)
    gat_gemm_tc<<<gg, 128>>>();

    dim3 g2(T_LEN / 128, B_SZ * H_CNT);         // (16, 32)
    gat_attn_mma<<<g2, 128>>>(out);
}

// round 14
// speedup vs baseline: 8.6782x; 1.0495x over previous
#include <cuda_runtime.h>
#include <cuda_fp16.h>
#include <cstdint>

// GraphAttentionLayer — all-tensor-core pipeline.
//   conv:  g_hh = fp16(h), g_W16 = fp16(W)
//   gemm:  g_Whh = fp16(g_hh @ g_W16)   (mma.sync fp16, cp.async-pipelined A)
//   attn:  flash attention (mma.sync fp16, ldmatrix single-tile, P in regs,
//          triple-buffer cp.async, one barrier/tile, row-sums via ones-MMA,
//          folded leaky+exp in log2 domain). Warp = m16 (64 q / CTA) for
//          3 CTAs/SM occupancy.

#define T_LEN   2048
#define B_SZ    8
#define H_CNT   4
#define D_DIM   64
#define IN_DIM  256
#define M_TOT   (B_SZ * T_LEN)

#define ONES2 0x3C003C00u   // fp16x2 {1.0, 1.0}

__device__ __half g_hh [(size_t)M_TOT * IN_DIM];   // 8 MB   fp16 h
__device__ __half g_W16[(size_t)IN_DIM * IN_DIM];  // 128 KB fp16 W
__device__ __half g_Whh[(size_t)M_TOT * IN_DIM];   // 8 MB   fp16 Wh

// ---------------------------------------------------------------------------
__device__ __forceinline__ uint32_t packh2(float lo, float hi) {
    uint32_t d;
    asm("cvt.rn.f16x2.f32 %0, %1, %2;" : "=r"(d) : "f"(hi), "f"(lo));
    return d;
}
__device__ __forceinline__ void mma16(float* c, const uint32_t* a,
                                      uint32_t b0, uint32_t b1) {
    asm volatile(
        "mma.sync.aligned.m16n8k16.row.col.f32.f16.f16.f32 "
        "{%0,%1,%2,%3}, {%4,%5,%6,%7}, {%8,%9}, {%0,%1,%2,%3};"
        : "+f"(c[0]), "+f"(c[1]), "+f"(c[2]), "+f"(c[3])
        : "r"(a[0]), "r"(a[1]), "r"(a[2]), "r"(a[3]), "r"(b0), "r"(b1));
}
// exp(leaky(s/8) - 8) = 2^( max(s, 0.2s)*log2e/8 - 8*log2e )
__device__ __forceinline__ float lexp(float s) {
    float m = fmaxf(s, 0.2f * s);
    float t = fmaf(m, 0.18033688011112043f, -11.541560327111708f);
    float r;
    asm("ex2.approx.ftz.f32 %0, %1;" : "=f"(r) : "f"(t));
    return r;
}
__device__ __forceinline__ uint32_t smem_addr(const void* p) {
    uint32_t a;
    asm("{ .reg .u64 t; cvta.to.shared.u64 t, %1; cvt.u32.u64 %0, t; }" : "=r"(a) : "l"(p));
    return a;
}
__device__ __forceinline__ void ldsm4(uint32_t& r0, uint32_t& r1, uint32_t& r2,
                                      uint32_t& r3, uint32_t addr) {
    asm volatile("ldmatrix.sync.aligned.m8n8.x4.shared.b16 {%0,%1,%2,%3}, [%4];"
                 : "=r"(r0), "=r"(r1), "=r"(r2), "=r"(r3) : "r"(addr));
}
__device__ __forceinline__ void ldsm4t(uint32_t& r0, uint32_t& r1, uint32_t& r2,
                                       uint32_t& r3, uint32_t addr) {
    asm volatile("ldmatrix.sync.aligned.m8n8.x4.trans.shared.b16 {%0,%1,%2,%3}, [%4];"
                 : "=r"(r0), "=r"(r1), "=r"(r2), "=r"(r3) : "r"(addr));
}
#define CP_ASYNC16(dst, src) \
    asm volatile("cp.async.cg.shared.global [%0], [%1], 16;" :: "r"(dst), "l"(src) : "memory")
#define CP_COMMIT() asm volatile("cp.async.commit_group;" ::: "memory")
#define CP_WAIT1()  asm volatile("cp.async.wait_group 1;" ::: "memory")
#define CP_WAIT0()  asm volatile("cp.async.wait_group 0;" ::: "memory")

// ---------------------------------------------------------------------------
// conv: fp32 -> fp16 for h and W
// ---------------------------------------------------------------------------
#define H4  ((M_TOT * IN_DIM) / 4)
#define W4  ((IN_DIM * IN_DIM) / 4)

__global__ void __launch_bounds__(256) gat_conv_kernel(
    const float4* __restrict__ h4, const float4* __restrict__ w4)
{
    const int i = blockIdx.x * 256 + threadIdx.x;
    if (i < H4) {
        float4 v = h4[i];
        ((uint2*)g_hh)[i] = make_uint2(packh2(v.x, v.y), packh2(v.z, v.w));
    } else if (i < H4 + W4) {
        const int j = i - H4;
        float4 v = w4[j];
        ((uint2*)g_W16)[j] = make_uint2(packh2(v.x, v.y), packh2(v.z, v.w));
    }
}

// ---------------------------------------------------------------------------
// Tensor GEMM: g_Whh[16384,256] = g_hh @ g_W16.  Grid (128, 4), 128 thr.
// W col-tile resident (32 KB, chunk c of row r at c^(r&7)); A streamed via
// triple-buffered cp.async 4 KB chunks (unit u = khalf*128 + row).
// ---------------------------------------------------------------------------
#define GW_WORDS 8192
#define GA_WORDS 1024
#define GA_BYTES 4096

__global__ void __launch_bounds__(128) gat_gemm_tc()
{
    __shared__ uint32_t smw[GW_WORDS + 3 * GA_WORDS];   // 44 KB
    const int tid = threadIdx.x;
    const int w   = tid >> 5;
    const int l   = tid & 31;
    const int g   = l >> 2;
    const int tig = l & 3;
    const int m0  = blockIdx.x * 128;
    const int n0  = blockIdx.y * 64;

    const uint32_t smbase = smem_addr(smw);
    const uint32_t abase  = smbase + GW_WORDS * 4;

#pragma unroll
    for (int rr = 0; rr < 2; rr++) {
        const int r = tid + 128 * rr;
        const char* src = (const char*)(g_W16 + (size_t)r * IN_DIM + n0);
#pragma unroll
        for (int c = 0; c < 8; c++)
            CP_ASYNC16(smbase + (uint32_t)(r * 128 + (((uint32_t)c ^ (r & 7)) << 4)),
                       src + 16 * c);
    }
    CP_COMMIT();

    const int au0 = tid, au1 = tid + 128;
    const int ac0 = au0 >> 7, ar0 = au0 & 127;
    const int ac1 = au1 >> 7, ar1 = au1 & 127;
    const char* asrc0 = (const char*)(g_hh + (size_t)(m0 + ar0) * IN_DIM + ac0 * 8);
    const char* asrc1 = (const char*)(g_hh + (size_t)(m0 + ar1) * IN_DIM + ac1 * 8);

#pragma unroll
    for (int k = 0; k < 2; k++) {
        const uint32_t bofs = (uint32_t)(k * GA_BYTES);
        CP_ASYNC16(abase + bofs + au0 * 16, asrc0 + (size_t)k * 32);
        CP_ASYNC16(abase + bofs + au1 * 16, asrc1 + (size_t)k * 32);
        CP_COMMIT();
    }

    float o[2][8][4];
#pragma unroll
    for (int hh = 0; hh < 2; hh++)
#pragma unroll
        for (int i = 0; i < 8; i++)
#pragma unroll
            for (int j = 0; j < 4; j++) o[hh][i][j] = 0.f;

    const uint32_t lk7  = (uint32_t)(l & 7);
    const int vKey = (((l >> 3) & 1) << 3) + (l & 7);
    const uint32_t vJ = (uint32_t)(l >> 4);
    const int aRow = w * 32 + (l & 15);
    const int aCol = l >> 4;

#pragma unroll
    for (int ks = 0; ks < 16; ks++) {
        if (ks < 15) CP_WAIT1(); else CP_WAIT0();
        __syncthreads();
        if (ks <= 13) {
            const uint32_t bofs = (uint32_t)(((ks + 2) % 3) * GA_BYTES);
            CP_ASYNC16(abase + bofs + au0 * 16, asrc0 + (size_t)(ks + 2) * 32);
            CP_ASYNC16(abase + bofs + au1 * 16, asrc1 + (size_t)(ks + 2) * 32);
            CP_COMMIT();
        }

        const uint32_t ab = abase + (uint32_t)((ks % 3) * GA_BYTES);
        uint32_t aa[2][4];
#pragma unroll
        for (int hh = 0; hh < 2; hh++)
            ldsm4(aa[hh][0], aa[hh][1], aa[hh][2], aa[hh][3],
                  ab + (uint32_t)(((aCol << 7) + aRow + hh * 16) << 4));

#pragma unroll
        for (int i = 0; i < 4; i++) {
            uint32_t r0, r1, r2, r3;
            const uint32_t addr = smbase + (uint32_t)((16 * ks + vKey) * 128
                                   + ((((uint32_t)(2 * i) + vJ) ^ lk7) << 4));
            ldsm4t(r0, r1, r2, r3, addr);
#pragma unroll
            for (int hh = 0; hh < 2; hh++) {
                mma16(o[hh][2 * i],     aa[hh], r0, r1);
                mma16(o[hh][2 * i + 1], aa[hh], r2, r3);
            }
        }
        __syncthreads();
    }

#pragma unroll
    for (int hh = 0; hh < 2; hh++) {
        const int row0 = m0 + w * 32 + hh * 16 + g;
        __half* p0 = g_Whh + (size_t)row0 * IN_DIM + n0;
        __half* p1 = p0 + 8 * IN_DIM;
#pragma unroll
        for (int j = 0; j < 8; j++) {
            const int col = 8 * j + 2 * tig;
            *(uint32_t*)(p0 + col) = packh2(o[hh][j][0], o[hh][j][1]);
            *(uint32_t*)(p1 + col) = packh2(o[hh][j][2], o[hh][j][3]);
        }
    }
}

// ---------------------------------------------------------------------------
// Flash attention. CTA = 128 thr (4 warps), warp = m16 (16 queries).
// CTA = 64 queries. Grid (32, 32) = 1024 CTAs. Key-tile 64, 32 tiles,
// triple-buffered cp.async, one barrier/tile. Row-sums via ones-MMA.
// Tile: row = key (64 x 128B), chunk c of row r at (c ^ (r & 7)).
// ---------------------------------------------------------------------------
#define BUF_BYTES 8192

__global__ void __launch_bounds__(128, 3) gat_attn_mma(float* __restrict__ out)
{
    __shared__ uint32_t smu[3 * BUF_BYTES / 4];   // 24 KB

    const int tid = threadIdx.x;
    const int w   = tid >> 5;
    const int l   = tid & 31;
    const int g   = l >> 2;
    const int tig = l & 3;

    const int bh = blockIdx.y, b = bh >> 2, head = bh & 3;
    const int qbase = blockIdx.x * 64;
    const __half* whh = g_Whh + (size_t)b * T_LEN * IN_DIM + head * D_DIM;

    const uint32_t smbase = smem_addr(smu);

    // fill setup (thread = half-row): 4 x cp.async 16B per tile
    const int frow = tid >> 1, fhf = tid & 1;
    const char* fsrc0 = (const char*)(whh + (size_t)frow * IN_DIM + fhf * 32);
    uint32_t fdst[4];
#pragma unroll
    for (int j = 0; j < 4; j++) {
        const int c = fhf * 4 + j;
        fdst[j] = smbase + (uint32_t)(frow * 128 + ((c ^ (frow & 7)) << 4));
    }

    // prologue: prefetch tiles 0 and 1
#pragma unroll
    for (int k = 0; k < 2; k++) {
        const char* s = fsrc0 + (size_t)k * 64 * IN_DIM * sizeof(__half);
        const uint32_t bofs = (uint32_t)(k * BUF_BYTES);
#pragma unroll
        for (int j = 0; j < 4; j++) CP_ASYNC16(fdst[j] + bofs, s + 16 * j);
        CP_COMMIT();
    }

    // Q fragments (warp = rows qbase + w*16 + g, +8)
    uint32_t qa[4][4];
    {
        const uint32_t* q0 = (const uint32_t*)(whh + (size_t)(qbase + w * 16 + g) * IN_DIM);
        const uint32_t* q1 = q0 + 8 * (IN_DIM / 2);
#pragma unroll
        for (int ks = 0; ks < 4; ks++) {
            qa[ks][0] = q0[8 * ks + tig];
            qa[ks][1] = q1[8 * ks + tig];
            qa[ks][2] = q0[8 * ks + 4 + tig];
            qa[ks][3] = q1[8 * ks + 4 + tig];
        }
    }

    float o[8][4];
#pragma unroll
    for (int i = 0; i < 8; i++)
#pragma unroll
        for (int j = 0; j < 4; j++) o[i][j] = 0.f;
    float lsacc[4] = {0.f, 0.f, 0.f, 0.f};

    const uint32_t lk7  = (uint32_t)(l & 7);
    const int sKey = ((l >> 4) << 3) + (l & 7);
    const uint32_t sSeg = (uint32_t)((l >> 3) & 1);
    const int vKey = (((l >> 3) & 1) << 3) + (l & 7);
    const uint32_t vJ  = (uint32_t)(l >> 4);

    for (int t = 0; t < 32; t++) {
        if (t < 31) CP_WAIT1(); else CP_WAIT0();
        __syncthreads();
        if (t <= 29) {
            const uint32_t bofs = (uint32_t)(((t + 2) % 3) * BUF_BYTES);
            const char* s = fsrc0 + (size_t)(t + 2) * 64 * IN_DIM * sizeof(__half);
#pragma unroll
            for (int j = 0; j < 4; j++) CP_ASYNC16(fdst[j] + bofs, s + 16 * j);
            CP_COMMIT();
        }

        const uint32_t bb = smbase + (uint32_t)((t % 3) * BUF_BYTES);

        // ---- S = Q K^T  (m16 x n64 x k64)
        float s2[8][4];
#pragma unroll
        for (int i = 0; i < 8; i++)
#pragma unroll
            for (int j = 0; j < 4; j++) s2[i][j] = 0.f;

#pragma unroll
        for (int ks = 0; ks < 4; ks++) {
#pragma unroll
            for (int i = 0; i < 4; i++) {
                uint32_t r0, r1, r2, r3;
                const uint32_t addr = bb + (uint32_t)((16 * i + sKey) * 128
                                       + ((((uint32_t)(2 * ks) + sSeg) ^ lk7) << 4));
                ldsm4(r0, r1, r2, r3, addr);
                mma16(s2[2 * i],     qa[ks], r0, r1);
                mma16(s2[2 * i + 1], qa[ks], r2, r3);
            }
        }

        // ---- epilogue: folded leaky+exp; P packed into registers
        uint32_t ph[8][2];
#pragma unroll
        for (int j = 0; j < 8; j++) {
            float p0 = lexp(s2[j][0]);
            float p1 = lexp(s2[j][1]);
            float p2 = lexp(s2[j][2]);
            float p3 = lexp(s2[j][3]);
            ph[j][0] = packh2(p0, p1);
            ph[j][1] = packh2(p2, p3);
        }

        // ---- O += P V ; row-sums += P * ones
#pragma unroll
        for (int ks = 0; ks < 4; ks++) {
            uint32_t pa[4] = { ph[2 * ks][0], ph[2 * ks][1],
                               ph[2 * ks + 1][0], ph[2 * ks + 1][1] };
#pragma unroll
            for (int i = 0; i < 4; i++) {
                uint32_t r0, r1, r2, r3;
                const uint32_t addr = bb + (uint32_t)((16 * ks + vKey) * 128
                                       + ((((uint32_t)(2 * i) + vJ) ^ lk7) << 4));
                ldsm4t(r0, r1, r2, r3, addr);
                mma16(o[2 * i],     pa, r0, r1);
                mma16(o[2 * i + 1], pa, r2, r3);
            }
            mma16(lsacc, pa, ONES2, ONES2);
        }
    }

    // ---- normalize + write (lsacc c0 = row g, c2 = row g+8)
    {
        const float inv0 = 1.0f / lsacc[0];
        const float inv1 = 1.0f / lsacc[2];
        const int row0 = qbase + w * 16 + g;
        float* p0 = out + (size_t)(b * T_LEN + row0) * IN_DIM + head * D_DIM;
        float* p1 = p0 + 8 * IN_DIM;
#pragma unroll
        for (int i = 0; i < 8; i++) {
            const int col = i * 8 + 2 * tig;
            *(float2*)(p0 + col) = make_float2(o[i][0] * inv0, o[i][1] * inv0);
            *(float2*)(p1 + col) = make_float2(o[i][2] * inv1, o[i][3] * inv1);
        }
    }
}

// ---------------------------------------------------------------------------

extern "C" void kernel_launch(void* const* d_in, const int* in_sizes, int n_in,
                              void* d_out, int out_size)
{
    const float* h = (const float*)d_in[0];
    const float* W = (const float*)d_in[1];
    float* out = (float*)d_out;

    gat_conv_kernel<<<(H4 + W4 + 255) / 256, 256>>>((const float4*)h, (const float4*)W);

    dim3 gg(M_TOT / 128, IN_DIM / 64);          // (128, 4)
    gat_gemm_tc<<<gg, 128>>>();

    dim3 g2(T_LEN / 64, B_SZ * H_CNT);          // (32, 32)
    gat_attn_mma<<<g2, 128>>>(out);
}